// round 13
// baseline (speedup 1.0000x reference)
#include <cuda_runtime.h>
#include <cstddef>
#include <cstdint>

#define Bc 48
#define Wn 8192
#define Fc 64
#define Dc 128
#define GRAM_CHUNKS 32
#define WT 128                            // w rows per tile
#define NTILES ((Wn / WT) * Bc)           // 3072
#define NCTA 152

typedef unsigned long long ull;

// device scratch (no runtime allocation allowed). 16B-aligned.
__device__ __align__(16) float g_gram_part[Bc * GRAM_CHUNKS * Fc * Fc];
__device__ __align__(16) float g_gram[Bc * Fc * Fc];          // tf32-rounded
__device__ __align__(16) float g_h[(size_t)Bc * Wn * Fc];     // tf32-rounded
__device__ __align__(16) float g_xr[(size_t)Bc * Wn * Fc];    // tf32-rounded x
__device__ __align__(16) float g_cwB[64 * 192];               // [f][k*64+g], tf32
__device__ __align__(16) float g_twB[128 * 192];              // [d][k*64+f], tf32
__device__ __align__(16) float g_sewr[Wn * Fc];               // seW rounded tf32

// ---------------------------------------------------------------------------
// packed f32x2 helpers (gram)
// ---------------------------------------------------------------------------
__device__ __forceinline__ ull dup2(float a) {
    ull r;
    asm("mov.b64 %0, {%1, %1};" : "=l"(r) : "r"(__float_as_uint(a)));
    return r;
}
__device__ __forceinline__ void unpack2(ull v, float& a, float& b) {
    unsigned lo, hi;
    asm("mov.b64 {%0, %1}, %2;" : "=r"(lo), "=r"(hi) : "l"(v));
    a = __uint_as_float(lo); b = __uint_as_float(hi);
}
__device__ __forceinline__ ull ffma2(ull a, ull b, ull c) {
    ull d;
    asm("fma.rn.f32x2 %0, %1, %2, %3;" : "=l"(d) : "l"(a), "l"(b), "l"(c));
    return d;
}

// ---------------------------------------------------------------------------
// tensor-core / async helpers (legacy paths — compile under compute_103)
// ---------------------------------------------------------------------------
__device__ __forceinline__ uint32_t smem_u32(const void* p) {
    uint32_t a;
    asm("{ .reg .u64 t; cvta.to.shared.u64 t, %1; cvt.u32.u64 %0, t; }" : "=r"(a) : "l"(p));
    return a;
}
__device__ __forceinline__ uint32_t cvt_tf32(float x) {
    uint32_t r;
    asm("cvt.rna.tf32.f32 %0, %1;" : "=r"(r) : "f"(x));
    return r;
}
__device__ __forceinline__ void cp_async16(uint32_t saddr, const void* gptr) {
    asm volatile("cp.async.ca.shared.global [%0], [%1], 16;" :: "r"(saddr), "l"(gptr));
}
__device__ __forceinline__ void cp_commit() {
    asm volatile("cp.async.commit_group;");
}
__device__ __forceinline__ void cp_wait1() {
    asm volatile("cp.async.wait_group 1;" ::: "memory");
}
__device__ __forceinline__ void cp_wait0() {
    asm volatile("cp.async.wait_group 0;" ::: "memory");
}
__device__ __forceinline__ void ldsm_x4(uint32_t addr, uint32_t* r) {
    asm volatile("ldmatrix.sync.aligned.m8n8.x4.shared.b16 {%0,%1,%2,%3}, [%4];"
                 : "=r"(r[0]), "=r"(r[1]), "=r"(r[2]), "=r"(r[3]) : "r"(addr));
}
__device__ __forceinline__ void mma_tf32(float* c, const uint32_t* a,
                                         uint32_t b0, uint32_t b1) {
    asm volatile(
        "mma.sync.aligned.m16n8k8.row.col.f32.tf32.tf32.f32 "
        "{%0,%1,%2,%3}, {%4,%5,%6,%7}, {%8,%9}, {%0,%1,%2,%3};"
        : "+f"(c[0]), "+f"(c[1]), "+f"(c[2]), "+f"(c[3])
        : "r"(a[0]), "r"(a[1]), "r"(a[2]), "r"(a[3]), "r"(b0), "r"(b1));
}

// ---------------------------------------------------------------------------
// Kernel 0: weight reorders + seW pre-rounding
// ---------------------------------------------------------------------------
__global__ void __launch_bounds__(256) prep_kernel(
    const float* __restrict__ ctx_w, const float* __restrict__ token_w,
    const float* __restrict__ seW_w) {
    int tid = blockIdx.x * 256 + threadIdx.x;
    int nt = gridDim.x * 256;
    for (int i = tid; i < 64 * 192; i += nt) {
        int f = i / 192, j = i - f * 192;
        int k = j >> 6, g = j & 63;
        g_cwB[i] = __uint_as_float(cvt_tf32(ctx_w[f * 192 + g * 3 + k]));
    }
    for (int i = tid; i < 128 * 192; i += nt) {
        int d = i / 192, j = i - d * 192;
        int k = j >> 6, f = j & 63;
        g_twB[i] = __uint_as_float(cvt_tf32(token_w[d * 192 + f * 3 + k]));
    }
    for (int i = tid; i < Wn * Fc / 4; i += nt) {
        float4 v = *((const float4*)seW_w + i);
        *((uint4*)g_sewr + i) =
            make_uint4(cvt_tf32(v.x), cvt_tf32(v.y), cvt_tf32(v.z), cvt_tf32(v.w));
    }
}

// ---------------------------------------------------------------------------
// Kernel 1: per-chunk partial Gram + writes tf32-rounded x to g_xr.
// ---------------------------------------------------------------------------
__global__ void __launch_bounds__(256) gram_partial(const float* __restrict__ x) {
    const int b = blockIdx.y;
    const int chunk = blockIdx.x;
    const int w_base = chunk * (Wn / GRAM_CHUNKS);

    __shared__ float xs[64][68];
    __shared__ float npart[4][64];
    __shared__ float sinv2[64];

    const int t = threadIdx.x;
    const int ti = t >> 4;
    const int tj = t & 15;

    ull acc[4][2];
    #pragma unroll
    for (int a = 0; a < 4; a++) { acc[a][0] = 0ull; acc[a][1] = 0ull; }

    const float* xb = x + (size_t)b * Wn * Fc;
    float* xrb = g_xr + (size_t)b * Wn * Fc;

    for (int tile = 0; tile < 256; tile += 64) {
        for (int i = t; i < 64 * 16; i += 256) {
            int r = i >> 4, c4 = i & 15;
            size_t gofs = (size_t)(w_base + tile + r) * Fc + c4 * 4;
            float4 v = *(const float4*)(xb + gofs);
            *(float4*)(&xs[r][c4 * 4]) = v;
            *(uint4*)(xrb + gofs) =
                make_uint4(cvt_tf32(v.x), cvt_tf32(v.y), cvt_tf32(v.z), cvt_tf32(v.w));
        }
        __syncthreads();
        {
            int q = t >> 6, r = t & 63;
            float s = 0.f;
            #pragma unroll
            for (int c = 0; c < 16; c++) { float v = xs[r][q * 16 + c]; s += v * v; }
            npart[q][r] = s;
        }
        __syncthreads();
        if (t < 64)
            sinv2[t] = 1.0f / (npart[0][t] + npart[1][t] + npart[2][t] + npart[3][t]);
        __syncthreads();

        #pragma unroll 4
        for (int w = 0; w < 64; w++) {
            float s = sinv2[w];
            const ull* row = (const ull*)(&xs[w][0]);
            ull vj0 = row[tj], vj1 = row[tj + 16];
            float vi0 = xs[w][ti] * s,      vi1 = xs[w][ti + 16] * s;
            float vi2 = xs[w][ti + 32] * s, vi3 = xs[w][ti + 48] * s;
            acc[0][0] = ffma2(dup2(vi0), vj0, acc[0][0]);
            acc[0][1] = ffma2(dup2(vi0), vj1, acc[0][1]);
            acc[1][0] = ffma2(dup2(vi1), vj0, acc[1][0]);
            acc[1][1] = ffma2(dup2(vi1), vj1, acc[1][1]);
            acc[2][0] = ffma2(dup2(vi2), vj0, acc[2][0]);
            acc[2][1] = ffma2(dup2(vi2), vj1, acc[2][1]);
            acc[3][0] = ffma2(dup2(vi3), vj0, acc[3][0]);
            acc[3][1] = ffma2(dup2(vi3), vj1, acc[3][1]);
        }
        __syncthreads();
    }

    float* dst = g_gram_part + ((size_t)b * GRAM_CHUNKS + chunk) * (Fc * Fc);
    #pragma unroll
    for (int a = 0; a < 4; a++)
        #pragma unroll
        for (int c = 0; c < 2; c++) {
            float u, v;
            unpack2(acc[a][c], u, v);
            *(float2*)(dst + (ti + 16 * a) * 64 + 2 * (tj + 16 * c)) = make_float2(u, v);
        }
}

__global__ void __launch_bounds__(256) gram_reduce() {
    const int b = blockIdx.x;
    const int t = threadIdx.x;
    for (int i = t; i < Fc * Fc; i += 256) {
        float s = 0.f;
        #pragma unroll
        for (int c = 0; c < GRAM_CHUNKS; c++)
            s += g_gram_part[((size_t)b * GRAM_CHUNKS + c) * (Fc * Fc) + i];
        g_gram[b * Fc * Fc + i] = __uint_as_float(cvt_tf32(s));
    }
}

// ---------------------------------------------------------------------------
// Kernel H (persistent, mma.sync tf32): 128w x 64f tiles, double-buffered A.
// 512 threads = 16 warps: 8 wgroups(16w) x 2 fgroups(32f) — warps independent.
// BC staged once; per-tile: AX (x rows), AS (seW rows), BG (gram).
// ---------------------------------------------------------------------------
#define HM_BC    0                        // 64*784  = 50176
// buf 0: AX 50176 (35360), AS 85536 (34816), BG 120352 (17408)
// buf 1: AX 137760,        AS 173120,        BG 207936 -> end 225344
#define HM_SMEM  225344

__global__ void __launch_bounds__(512, 1) h_mma_kernel(
    const float* __restrict__ ctx_b,
    const float* __restrict__ seW_b)
{
    extern __shared__ char smc[];
    uint32_t sbase = smem_u32(smc);
    const int t   = threadIdx.x;
    const int wid = t >> 5;
    const int l   = t & 31;

    const uint32_t AXo[2] = {50176u, 137760u};
    const uint32_t ASo[2] = {85536u, 173120u};
    const uint32_t BGo[2] = {120352u, 207936u};

    int per = NTILES / gridDim.x, rem = NTILES % gridDim.x;
    int cta = blockIdx.x;
    int start = cta * per + (cta < rem ? cta : rem);
    int cnt = per + (cta < rem ? 1 : 0);
    if (cnt == 0) return;

    // ---- stage BC (once) + tile `start` into buf 0 ----
    for (int i = t; i < 64 * 48; i += 512) {
        int f = i / 48, c4 = i - f * 48;
        cp_async16(sbase + HM_BC + f * 784 + c4 * 16, g_cwB + f * 192 + c4 * 4);
    }
    {
        int tau = start;
        int bb = tau >> 6, w0 = (tau & 63) * WT;
        const float* xrb = g_xr + (size_t)bb * Wn * Fc;
        for (int i = t; i < 130 * 16; i += 512) {
            int j = i >> 4, c4 = i & 15;
            int gr = w0 - 1 + j;
            if (gr >= 0 && gr < Wn)
                cp_async16(sbase + AXo[0] + j * 272 + c4 * 16, xrb + (size_t)gr * Fc + c4 * 4);
            else
                *(uint4*)(smc + AXo[0] + j * 272 + c4 * 16) = make_uint4(0, 0, 0, 0);
        }
        for (int i = t; i < 128 * 16; i += 512) {
            int r = i >> 4, c4 = i & 15;
            cp_async16(sbase + ASo[0] + r * 272 + c4 * 16,
                       g_sewr + (size_t)(w0 + r) * Fc + c4 * 4);
        }
        for (int i = t; i < 64 * 16; i += 512) {
            int f = i >> 4, c4 = i & 15;
            cp_async16(sbase + BGo[0] + f * 272 + c4 * 16,
                       g_gram + bb * 4096 + f * 64 + c4 * 4);
        }
    }
    cp_commit();

    // per-warp constants: warp tile 16w x 32f
    const int wg = wid >> 1;               // 0..7, R = wg*16
    const int fg = wid & 1;                // f0 = fg*32
    const int R  = wg * 16;
    const int f0 = fg * 32;
    const int a_row_in = (l & 7) + ((l >> 3) & 1) * 8;
    const uint32_t a_col = (uint32_t)(l >> 4) * 16;
    const int b_row_in = (l & 7) + (l >> 4) * 8;
    const uint32_t b_col = (uint32_t)((l >> 3) & 1) * 16;
    const uint32_t aBC = sbase + HM_BC + (uint32_t)(f0 + b_row_in) * 784 + b_col;
    const int gr  = l >> 2;
    const int gc2 = (l & 3) * 2;

    for (int it = 0; it < cnt; it++) {
        int buf = it & 1;
        // ---- prefetch next tile into other buffer ----
        if (it + 1 < cnt) {
            int tau = start + it + 1;
            int bb = tau >> 6, w0 = (tau & 63) * WT;
            int nb = buf ^ 1;
            const float* xrb = g_xr + (size_t)bb * Wn * Fc;
            for (int i = t; i < 130 * 16; i += 512) {
                int j = i >> 4, c4 = i & 15;
                int grr = w0 - 1 + j;
                if (grr >= 0 && grr < Wn)
                    cp_async16(sbase + AXo[nb] + j * 272 + c4 * 16,
                               xrb + (size_t)grr * Fc + c4 * 4);
                else
                    *(uint4*)(smc + AXo[nb] + j * 272 + c4 * 16) = make_uint4(0, 0, 0, 0);
            }
            for (int i = t; i < 128 * 16; i += 512) {
                int r = i >> 4, c4 = i & 15;
                cp_async16(sbase + ASo[nb] + r * 272 + c4 * 16,
                           g_sewr + (size_t)(w0 + r) * Fc + c4 * 4);
            }
            for (int i = t; i < 64 * 16; i += 512) {
                int f = i >> 4, c4 = i & 15;
                cp_async16(sbase + BGo[nb] + f * 272 + c4 * 16,
                           g_gram + bb * 4096 + f * 64 + c4 * 4);
            }
            cp_commit();
            cp_wait1();
        } else {
            cp_wait0();
        }
        __syncthreads();

        // ---- compute tile it from buf ----
        int tau = start + it;
        int bb = tau >> 6, w0 = (tau & 63) * WT;
        uint32_t aAX = sbase + AXo[buf] + (uint32_t)(R + a_row_in) * 272 + a_col;
        uint32_t aAS = sbase + ASo[buf] + (uint32_t)(R + a_row_in) * 272 + a_col;
        uint32_t aBG = sbase + BGo[buf] + (uint32_t)(f0 + b_row_in) * 272 + b_col;

        float acc[4][4];                   // [n-tile][frag], single m-tile (16w)
        #pragma unroll
        for (int j = 0; j < 4; j++)
            #pragma unroll
            for (int q = 0; q < 4; q++) acc[j][q] = 0.f;

        // SE GEMM: K=64
        #pragma unroll
        for (int s = 0; s < 8; s++) {
            uint32_t fa[4], fb0[4], fb1[4];
            ldsm_x4(aAS + 32u * s, fa);
            ldsm_x4(aBG + 32u * s, fb0);
            ldsm_x4(aBG + 16u * 272 + 32u * s, fb1);
            mma_tf32(acc[0], fa, fb0[0], fb0[1]);
            mma_tf32(acc[1], fa, fb0[2], fb0[3]);
            mma_tf32(acc[2], fa, fb1[0], fb1[1]);
            mma_tf32(acc[3], fa, fb1[2], fb1[3]);
        }

        // transform in place: acc = relu(acc + seb) + ctx_b
        {
            int row0 = w0 + R + gr;
            float s0 = __ldg(seW_b + row0);
            float s1 = __ldg(seW_b + row0 + 8);
            #pragma unroll
            for (int ntile = 0; ntile < 4; ntile++) {
                int col = f0 + ntile * 8 + gc2;
                float c0 = __ldg(ctx_b + col), c1 = __ldg(ctx_b + col + 1);
                float* a = acc[ntile];
                a[0] = fmaxf(a[0] + s0, 0.f) + c0;
                a[1] = fmaxf(a[1] + s0, 0.f) + c1;
                a[2] = fmaxf(a[2] + s1, 0.f) + c0;
                a[3] = fmaxf(a[3] + s1, 0.f) + c1;
            }
        }

        // conv GEMM: 3 passes x K=64
        #pragma unroll
        for (int pass = 0; pass < 3; pass++) {
            uint32_t abase = aAX + (uint32_t)pass * 272;
            uint32_t bbase = aBC + (uint32_t)pass * 256;
            #pragma unroll
            for (int s = 0; s < 8; s++) {
                uint32_t fa[4], fb0[4], fb1[4];
                ldsm_x4(abase + 32u * s, fa);
                ldsm_x4(bbase + 32u * s, fb0);
                ldsm_x4(bbase + 16u * 784 + 32u * s, fb1);
                mma_tf32(acc[0], fa, fb0[0], fb0[1]);
                mma_tf32(acc[1], fa, fb0[2], fb0[3]);
                mma_tf32(acc[2], fa, fb1[0], fb1[1]);
                mma_tf32(acc[3], fa, fb1[2], fb1[3]);
            }
        }

        // store h (tf32-rounded)
        {
            int row0 = w0 + R + gr;
            #pragma unroll
            for (int ntile = 0; ntile < 4; ntile++) {
                const float* a = acc[ntile];
                float* h0 = g_h + ((size_t)bb * Wn + row0) * Fc + f0 + ntile * 8 + gc2;
                *(uint2*)(h0) = make_uint2(cvt_tf32(a[0]), cvt_tf32(a[1]));
                *(uint2*)(h0 + 8 * Fc) = make_uint2(cvt_tf32(a[2]), cvt_tf32(a[3]));
            }
        }
        __syncthreads();
    }
}

// ---------------------------------------------------------------------------
// Kernel O (persistent, mma.sync tf32): 128w x 128d tiles, double-buffered A.
// 512 threads = 16 warps: 4 wgroups(32w) x 4 dgroups(32d) — warps independent.
// B staged once; per-tile: A (h rows, circular).
// ---------------------------------------------------------------------------
#define OM_B     0                        // 128*784 = 100352
// buf 0: A 100352 (35360); buf 1: A 135712 -> end 171072
#define OM_SMEM  171072

__global__ void __launch_bounds__(512, 1) out_mma_kernel(float* __restrict__ out)
{
    extern __shared__ char smc[];
    uint32_t sbase = smem_u32(smc);
    const int t   = threadIdx.x;
    const int wid = t >> 5;
    const int l   = t & 31;

    const uint32_t Ao[2] = {100352u, 135712u};

    int per = NTILES / gridDim.x, rem = NTILES % gridDim.x;
    int cta = blockIdx.x;
    int start = cta * per + (cta < rem ? cta : rem);
    int cnt = per + (cta < rem ? 1 : 0);
    if (cnt == 0) return;

    for (int i = t; i < 128 * 48; i += 512) {
        int d = i / 48, c4 = i - d * 48;
        cp_async16(sbase + OM_B + d * 784 + c4 * 16, g_twB + d * 192 + c4 * 4);
    }
    {
        int tau = start;
        int bb = tau >> 6, w0 = (tau & 63) * WT;
        const float* hb = g_h + (size_t)bb * Wn * Fc;
        for (int i = t; i < 130 * 16; i += 512) {
            int j = i >> 4, c4 = i & 15;
            int gw = (w0 - 1 + j + Wn) & (Wn - 1);
            cp_async16(sbase + Ao[0] + j * 272 + c4 * 16, hb + (size_t)gw * Fc + c4 * 4);
        }
    }
    cp_commit();

    const int wg = wid & 3;                // R = wg*32
    const int dg = wid >> 2;               // D = dg*32
    const int R  = wg * 32;
    const int D  = dg * 32;
    const int a_row_in = (l & 7) + ((l >> 3) & 1) * 8;
    const uint32_t a_col = (uint32_t)(l >> 4) * 16;
    const int b_d_in = (l & 7) + (l >> 4) * 8;
    const uint32_t aB = sbase + OM_B + (uint32_t)(D + b_d_in) * 784
                        + (uint32_t)((l >> 3) & 1) * 16;
    const int gr  = l >> 2;
    const int gc2 = (l & 3) * 2;

    for (int it = 0; it < cnt; it++) {
        int buf = it & 1;
        if (it + 1 < cnt) {
            int tau = start + it + 1;
            int bb = tau >> 6, w0 = (tau & 63) * WT;
            int nb = buf ^ 1;
            const float* hb = g_h + (size_t)bb * Wn * Fc;
            for (int i = t; i < 130 * 16; i += 512) {
                int j = i >> 4, c4 = i & 15;
                int gw = (w0 - 1 + j + Wn) & (Wn - 1);
                cp_async16(sbase + Ao[nb] + j * 272 + c4 * 16,
                           hb + (size_t)gw * Fc + c4 * 4);
            }
            cp_commit();
            cp_wait1();
        } else {
            cp_wait0();
        }
        __syncthreads();

        int tau = start + it;
        int bb = tau >> 6, w0 = (tau & 63) * WT;
        uint32_t aA = sbase + Ao[buf] + (uint32_t)(R + a_row_in) * 272 + a_col;

        float acc[2][4][4];                // [m-tile][n-tile][frag]
        #pragma unroll
        for (int i = 0; i < 2; i++)
            #pragma unroll
            for (int j = 0; j < 4; j++)
                #pragma unroll
                for (int q = 0; q < 4; q++) acc[i][j][q] = 0.f;

        #pragma unroll
        for (int pass = 0; pass < 3; pass++) {
            uint32_t abase = aA + (uint32_t)pass * 272;
            uint32_t bbase = aB + (uint32_t)pass * 256;
            #pragma unroll
            for (int s = 0; s < 8; s++) {
                uint32_t fa0[4], fa1[4], fb0[4], fb1[4];
                ldsm_x4(abase + 32u * s, fa0);
                ldsm_x4(abase + 16u * 272 + 32u * s, fa1);
                ldsm_x4(bbase + 32u * s, fb0);
                ldsm_x4(bbase + 16u * 784 + 32u * s, fb1);
                mma_tf32(acc[0][0], fa0, fb0[0], fb0[1]);
                mma_tf32(acc[0][1], fa0, fb0[2], fb0[3]);
                mma_tf32(acc[0][2], fa0, fb1[0], fb1[1]);
                mma_tf32(acc[0][3], fa0, fb1[2], fb1[3]);
                mma_tf32(acc[1][0], fa1, fb0[0], fb0[1]);
                mma_tf32(acc[1][1], fa1, fb0[2], fb0[3]);
                mma_tf32(acc[1][2], fa1, fb1[0], fb1[1]);
                mma_tf32(acc[1][3], fa1, fb1[2], fb1[3]);
            }
        }

        #pragma unroll
        for (int mt = 0; mt < 2; mt++) {
            #pragma unroll
            for (int ntile = 0; ntile < 4; ntile++) {
                const float* c = acc[mt][ntile];
                int w_row = w0 + R + mt * 16 + gr;
                int d_col = D + ntile * 8 + gc2;
                float* ob = out + ((size_t)bb * Wn + w_row) * Dc + d_col;
                *(float2*)(ob)          = make_float2(c[0], c[1]);
                *(float2*)(ob + 8 * Dc) = make_float2(c[2], c[3]);
            }
        }
        __syncthreads();
    }
}

// ---------------------------------------------------------------------------
extern "C" void kernel_launch(void* const* d_in, const int* in_sizes, int n_in,
                              void* d_out, int out_size) {
    const float* x       = (const float*)d_in[0];
    const float* ctx_w   = (const float*)d_in[1];
    const float* ctx_b   = (const float*)d_in[2];
    const float* token_w = (const float*)d_in[3];
    const float* seW_w   = (const float*)d_in[4];
    const float* seW_b   = (const float*)d_in[5];
    float* out = (float*)d_out;

    cudaFuncSetAttribute(h_mma_kernel,
                         cudaFuncAttributeMaxDynamicSharedMemorySize, HM_SMEM);
    cudaFuncSetAttribute(out_mma_kernel,
                         cudaFuncAttributeMaxDynamicSharedMemorySize, OM_SMEM);

    gram_partial<<<dim3(GRAM_CHUNKS, Bc), 256>>>(x);
    prep_kernel<<<96, 256>>>(ctx_w, token_w, seW_w);
    gram_reduce<<<Bc, 256>>>();
    h_mma_kernel<<<NCTA, 512, HM_SMEM>>>(ctx_b, seW_b);
    out_mma_kernel<<<NCTA, 512, OM_SMEM>>>(out);
}

// round 14
// speedup vs baseline: 1.0426x; 1.0426x over previous
#include <cuda_runtime.h>
#include <cstddef>
#include <cstdint>

#define Bc 48
#define Wn 8192
#define Fc 64
#define Dc 128
#define GRAM_CHUNKS 32

typedef unsigned long long ull;

// device scratch (no runtime allocation allowed). 16B-aligned.
__device__ __align__(16) float g_gram_part[Bc * GRAM_CHUNKS * Fc * Fc];
__device__ __align__(16) float g_gram[Bc * Fc * Fc];          // tf32-rounded
__device__ __align__(16) float g_h[(size_t)Bc * Wn * Fc];     // tf32-rounded
__device__ __align__(16) float g_xr[(size_t)Bc * Wn * Fc];    // tf32-rounded x
__device__ __align__(16) float g_cwB[64 * 192];               // [f][k*64+g], tf32
__device__ __align__(16) float g_twB[128 * 192];              // [d][k*64+f], tf32
__device__ __align__(16) float g_sewr[Wn * Fc];               // seW rounded tf32

// ---------------------------------------------------------------------------
// packed f32x2 helpers (gram)
// ---------------------------------------------------------------------------
__device__ __forceinline__ ull dup2(float a) {
    ull r;
    asm("mov.b64 %0, {%1, %1};" : "=l"(r) : "r"(__float_as_uint(a)));
    return r;
}
__device__ __forceinline__ void unpack2(ull v, float& a, float& b) {
    unsigned lo, hi;
    asm("mov.b64 {%0, %1}, %2;" : "=r"(lo), "=r"(hi) : "l"(v));
    a = __uint_as_float(lo); b = __uint_as_float(hi);
}
__device__ __forceinline__ ull ffma2(ull a, ull b, ull c) {
    ull d;
    asm("fma.rn.f32x2 %0, %1, %2, %3;" : "=l"(d) : "l"(a), "l"(b), "l"(c));
    return d;
}

// ---------------------------------------------------------------------------
// tensor-core / async helpers (legacy paths — compile under compute_103)
// ---------------------------------------------------------------------------
__device__ __forceinline__ uint32_t smem_u32(const void* p) {
    uint32_t a;
    asm("{ .reg .u64 t; cvta.to.shared.u64 t, %1; cvt.u32.u64 %0, t; }" : "=r"(a) : "l"(p));
    return a;
}
__device__ __forceinline__ uint32_t cvt_tf32(float x) {
    uint32_t r;
    asm("cvt.rna.tf32.f32 %0, %1;" : "=r"(r) : "f"(x));
    return r;
}
__device__ __forceinline__ void cp_async16(uint32_t saddr, const void* gptr) {
    asm volatile("cp.async.ca.shared.global [%0], [%1], 16;" :: "r"(saddr), "l"(gptr));
}
__device__ __forceinline__ void cp_commit() {
    asm volatile("cp.async.commit_group;");
}
__device__ __forceinline__ void cp_wait0() {
    asm volatile("cp.async.wait_group 0;" ::: "memory");
}
__device__ __forceinline__ void ldsm_x4(uint32_t addr, uint32_t* r) {
    asm volatile("ldmatrix.sync.aligned.m8n8.x4.shared.b16 {%0,%1,%2,%3}, [%4];"
                 : "=r"(r[0]), "=r"(r[1]), "=r"(r[2]), "=r"(r[3]) : "r"(addr));
}
__device__ __forceinline__ void mma_tf32(float* c, const uint32_t* a,
                                         uint32_t b0, uint32_t b1) {
    asm volatile(
        "mma.sync.aligned.m16n8k8.row.col.f32.tf32.tf32.f32 "
        "{%0,%1,%2,%3}, {%4,%5,%6,%7}, {%8,%9}, {%0,%1,%2,%3};"
        : "+f"(c[0]), "+f"(c[1]), "+f"(c[2]), "+f"(c[3])
        : "r"(a[0]), "r"(a[1]), "r"(a[2]), "r"(a[3]), "r"(b0), "r"(b1));
}

// ---------------------------------------------------------------------------
// Kernel 0: weight reorders + seW pre-rounding
// ---------------------------------------------------------------------------
__global__ void __launch_bounds__(256) prep_kernel(
    const float* __restrict__ ctx_w, const float* __restrict__ token_w,
    const float* __restrict__ seW_w) {
    int tid = blockIdx.x * 256 + threadIdx.x;
    int nt = gridDim.x * 256;
    for (int i = tid; i < 64 * 192; i += nt) {
        int f = i / 192, j = i - f * 192;
        int k = j >> 6, g = j & 63;
        g_cwB[i] = __uint_as_float(cvt_tf32(ctx_w[f * 192 + g * 3 + k]));
    }
    for (int i = tid; i < 128 * 192; i += nt) {
        int d = i / 192, j = i - d * 192;
        int k = j >> 6, f = j & 63;
        g_twB[i] = __uint_as_float(cvt_tf32(token_w[d * 192 + f * 3 + k]));
    }
    for (int i = tid; i < Wn * Fc / 4; i += nt) {
        float4 v = *((const float4*)seW_w + i);
        *((uint4*)g_sewr + i) =
            make_uint4(cvt_tf32(v.x), cvt_tf32(v.y), cvt_tf32(v.z), cvt_tf32(v.w));
    }
}

// ---------------------------------------------------------------------------
// Kernel 1: per-chunk partial Gram + writes tf32-rounded x to g_xr.
// ---------------------------------------------------------------------------
__global__ void __launch_bounds__(256) gram_partial(const float* __restrict__ x) {
    const int b = blockIdx.y;
    const int chunk = blockIdx.x;
    const int w_base = chunk * (Wn / GRAM_CHUNKS);

    __shared__ float xs[64][68];
    __shared__ float npart[4][64];
    __shared__ float sinv2[64];

    const int t = threadIdx.x;
    const int ti = t >> 4;
    const int tj = t & 15;

    ull acc[4][2];
    #pragma unroll
    for (int a = 0; a < 4; a++) { acc[a][0] = 0ull; acc[a][1] = 0ull; }

    const float* xb = x + (size_t)b * Wn * Fc;
    float* xrb = g_xr + (size_t)b * Wn * Fc;

    for (int tile = 0; tile < 256; tile += 64) {
        for (int i = t; i < 64 * 16; i += 256) {
            int r = i >> 4, c4 = i & 15;
            size_t gofs = (size_t)(w_base + tile + r) * Fc + c4 * 4;
            float4 v = *(const float4*)(xb + gofs);
            *(float4*)(&xs[r][c4 * 4]) = v;
            *(uint4*)(xrb + gofs) =
                make_uint4(cvt_tf32(v.x), cvt_tf32(v.y), cvt_tf32(v.z), cvt_tf32(v.w));
        }
        __syncthreads();
        {
            int q = t >> 6, r = t & 63;
            float s = 0.f;
            #pragma unroll
            for (int c = 0; c < 16; c++) { float v = xs[r][q * 16 + c]; s += v * v; }
            npart[q][r] = s;
        }
        __syncthreads();
        if (t < 64)
            sinv2[t] = 1.0f / (npart[0][t] + npart[1][t] + npart[2][t] + npart[3][t]);
        __syncthreads();

        #pragma unroll 4
        for (int w = 0; w < 64; w++) {
            float s = sinv2[w];
            const ull* row = (const ull*)(&xs[w][0]);
            ull vj0 = row[tj], vj1 = row[tj + 16];
            float vi0 = xs[w][ti] * s,      vi1 = xs[w][ti + 16] * s;
            float vi2 = xs[w][ti + 32] * s, vi3 = xs[w][ti + 48] * s;
            acc[0][0] = ffma2(dup2(vi0), vj0, acc[0][0]);
            acc[0][1] = ffma2(dup2(vi0), vj1, acc[0][1]);
            acc[1][0] = ffma2(dup2(vi1), vj0, acc[1][0]);
            acc[1][1] = ffma2(dup2(vi1), vj1, acc[1][1]);
            acc[2][0] = ffma2(dup2(vi2), vj0, acc[2][0]);
            acc[2][1] = ffma2(dup2(vi2), vj1, acc[2][1]);
            acc[3][0] = ffma2(dup2(vi3), vj0, acc[3][0]);
            acc[3][1] = ffma2(dup2(vi3), vj1, acc[3][1]);
        }
        __syncthreads();
    }

    float* dst = g_gram_part + ((size_t)b * GRAM_CHUNKS + chunk) * (Fc * Fc);
    #pragma unroll
    for (int a = 0; a < 4; a++)
        #pragma unroll
        for (int c = 0; c < 2; c++) {
            float u, v;
            unpack2(acc[a][c], u, v);
            *(float2*)(dst + (ti + 16 * a) * 64 + 2 * (tj + 16 * c)) = make_float2(u, v);
        }
}

__global__ void __launch_bounds__(256) gram_reduce() {
    const int b = blockIdx.x;
    const int t = threadIdx.x;
    for (int i = t; i < Fc * Fc; i += 256) {
        float s = 0.f;
        #pragma unroll
        for (int c = 0; c < GRAM_CHUNKS; c++)
            s += g_gram_part[((size_t)b * GRAM_CHUNKS + c) * (Fc * Fc) + i];
        g_gram[b * Fc * Fc + i] = __uint_as_float(cvt_tf32(s));
    }
}

// ---------------------------------------------------------------------------
// Kernel H (mma.sync tf32): R11 winner config, verbatim.
// 256w x 64f per CTA, 16 warps = 8 wgroups(32w) x 2 fgroups(32f).
// ---------------------------------------------------------------------------
#define HM_AX   0                         // 258*272 = 70176 (stride 68 words)
#define HM_AS   70176                     // 256*272 = 69632
#define HM_BC   139808                    // 64*784  = 50176
#define HM_BG   189984                    // 64*272  = 17408
#define HM_SMEM 207392

__global__ void __launch_bounds__(512, 1) h_mma_kernel(
    const float* __restrict__ ctx_b,
    const float* __restrict__ seW_b)
{
    extern __shared__ char smc[];
    uint32_t sbase = smem_u32(smc);
    const int t   = threadIdx.x;
    const int wid = t >> 5;
    const int l   = t & 31;
    const int b   = blockIdx.y;
    const int w0  = blockIdx.x * 256;

    const float* xrb = g_xr + (size_t)b * Wn * Fc;

    // ---- staging (one group) ----
    for (int i = t; i < 64 * 48; i += 512) {             // BC
        int f = i / 48, c4 = i - f * 48;
        cp_async16(sbase + HM_BC + f * 784 + c4 * 16, g_cwB + f * 192 + c4 * 4);
    }
    for (int i = t; i < 64 * 16; i += 512) {             // BG
        int f = i >> 4, c4 = i & 15;
        cp_async16(sbase + HM_BG + f * 272 + c4 * 16, g_gram + b * 4096 + f * 64 + c4 * 4);
    }
    for (int i = t; i < 256 * 16; i += 512) {            // AS rows 0..255
        int r = i >> 4, c4 = i & 15;
        cp_async16(sbase + HM_AS + r * 272 + c4 * 16,
                   g_sewr + (size_t)(w0 + r) * Fc + c4 * 4);
    }
    for (int i = t; i < 258 * 16; i += 512) {            // AX rows 0..257
        int j = i >> 4, c4 = i & 15;
        int gr = w0 - 1 + j;
        if (gr >= 0 && gr < Wn)
            cp_async16(sbase + HM_AX + j * 272 + c4 * 16, xrb + (size_t)gr * Fc + c4 * 4);
        else
            *(uint4*)(smc + HM_AX + j * 272 + c4 * 16) = make_uint4(0, 0, 0, 0);
    }
    cp_commit();

    const int fg = wid & 1;                // f0 = fg*32
    const int wg = wid >> 1;               // R = wg*32
    const int R  = wg * 32;
    const int f0 = fg * 32;

    const int a_row_in = (l & 7) + ((l >> 3) & 1) * 8;
    const uint32_t a_col = (uint32_t)(l >> 4) * 16;
    const int b_row_in = (l & 7) + (l >> 4) * 8;
    const uint32_t b_col = (uint32_t)((l >> 3) & 1) * 16;
    uint32_t aBC = sbase + HM_BC + (uint32_t)(f0 + b_row_in) * 784 + b_col;
    uint32_t aBG = sbase + HM_BG + (uint32_t)(f0 + b_row_in) * 272 + b_col;
    uint32_t aAX = sbase + HM_AX + (uint32_t)(R + a_row_in) * 272 + a_col;
    uint32_t aAS = sbase + HM_AS + (uint32_t)(R + a_row_in) * 272 + a_col;

    const int gr  = l >> 2;
    const int gc2 = (l & 3) * 2;

    float acc[2][4][4];                    // [m-tile][n-tile][frag]
    #pragma unroll
    for (int i = 0; i < 2; i++)
        #pragma unroll
        for (int j = 0; j < 4; j++)
            #pragma unroll
            for (int q = 0; q < 4; q++) acc[i][j][q] = 0.f;

    cp_wait0();
    __syncthreads();

    // ---- SE GEMM: K=64 ----
    #pragma unroll
    for (int s = 0; s < 8; s++) {
        uint32_t fa0[4], fa1[4], fb0[4], fb1[4];
        ldsm_x4(aAS + 32u * s, fa0);
        ldsm_x4(aAS + 16u * 272 + 32u * s, fa1);
        ldsm_x4(aBG + 32u * s, fb0);
        ldsm_x4(aBG + 16u * 272 + 32u * s, fb1);
        mma_tf32(acc[0][0], fa0, fb0[0], fb0[1]);
        mma_tf32(acc[0][1], fa0, fb0[2], fb0[3]);
        mma_tf32(acc[0][2], fa0, fb1[0], fb1[1]);
        mma_tf32(acc[0][3], fa0, fb1[2], fb1[3]);
        mma_tf32(acc[1][0], fa1, fb0[0], fb0[1]);
        mma_tf32(acc[1][1], fa1, fb0[2], fb0[3]);
        mma_tf32(acc[1][2], fa1, fb1[0], fb1[1]);
        mma_tf32(acc[1][3], fa1, fb1[2], fb1[3]);
    }

    // ---- transform in place: acc = relu(acc + seb) + ctx_b ----
    {
        int row0 = w0 + R + gr;
        float seb[4];
        seb[0] = __ldg(seW_b + row0);
        seb[1] = __ldg(seW_b + row0 + 8);
        seb[2] = __ldg(seW_b + row0 + 16);
        seb[3] = __ldg(seW_b + row0 + 24);
        #pragma unroll
        for (int mt = 0; mt < 2; mt++) {
            float s0 = seb[mt * 2], s1 = seb[mt * 2 + 1];
            #pragma unroll
            for (int ntile = 0; ntile < 4; ntile++) {
                int col = f0 + ntile * 8 + gc2;
                float c0 = __ldg(ctx_b + col), c1 = __ldg(ctx_b + col + 1);
                float* a = acc[mt][ntile];
                a[0] = fmaxf(a[0] + s0, 0.f) + c0;
                a[1] = fmaxf(a[1] + s0, 0.f) + c1;
                a[2] = fmaxf(a[2] + s1, 0.f) + c0;
                a[3] = fmaxf(a[3] + s1, 0.f) + c1;
            }
        }
    }

    // ---- conv GEMM: 3 passes x K=64 ----
    #pragma unroll
    for (int pass = 0; pass < 3; pass++) {
        uint32_t abase = aAX + (uint32_t)pass * 272;
        uint32_t bbase = aBC + (uint32_t)pass * 256;
        #pragma unroll
        for (int s = 0; s < 8; s++) {
            uint32_t fa0[4], fa1[4], fb0[4], fb1[4];
            ldsm_x4(abase + 32u * s, fa0);
            ldsm_x4(abase + 16u * 272 + 32u * s, fa1);
            ldsm_x4(bbase + 32u * s, fb0);
            ldsm_x4(bbase + 16u * 784 + 32u * s, fb1);
            mma_tf32(acc[0][0], fa0, fb0[0], fb0[1]);
            mma_tf32(acc[0][1], fa0, fb0[2], fb0[3]);
            mma_tf32(acc[0][2], fa0, fb1[0], fb1[1]);
            mma_tf32(acc[0][3], fa0, fb1[2], fb1[3]);
            mma_tf32(acc[1][0], fa1, fb0[0], fb0[1]);
            mma_tf32(acc[1][1], fa1, fb0[2], fb0[3]);
            mma_tf32(acc[1][2], fa1, fb1[0], fb1[1]);
            mma_tf32(acc[1][3], fa1, fb1[2], fb1[3]);
        }
    }

    // ---- store h (tf32-rounded) ----
    #pragma unroll
    for (int mt = 0; mt < 2; mt++) {
        int row0 = w0 + R + mt * 16 + gr;
        #pragma unroll
        for (int ntile = 0; ntile < 4; ntile++) {
            const float* a = acc[mt][ntile];
            float* h0 = g_h + ((size_t)b * Wn + row0) * Fc + f0 + ntile * 8 + gc2;
            *(uint2*)(h0) = make_uint2(cvt_tf32(a[0]), cvt_tf32(a[1]));
            *(uint2*)(h0 + 8 * Fc) = make_uint2(cvt_tf32(a[2]), cvt_tf32(a[3]));
        }
    }
}

// ---------------------------------------------------------------------------
// Kernel O (persistent, mma.sync tf32, d-split for 2 CTAs/SM):
// grid = 304; CTAs [0,152) handle d 0..63, [152,304) handle d 64..127.
// Each CTA: 256 threads = 8 warps (4 wgroups(32w) x 2 dgroups(32d)),
// B-half (50 KB) staged once, A (128w tile, 35 KB) single-buffered —
// the co-resident sibling CTA hides staging latency + dependency stalls.
// ---------------------------------------------------------------------------
#define OMS_B    0                        // 64*784 = 50176
#define OMS_A    50176                    // 130*272 = 35360
#define OMS_SMEM 85536
#define O_NT     3072                     // w-tiles (b * 64 + w0/128)

__global__ void __launch_bounds__(256, 2) out_mma_kernel(float* __restrict__ out)
{
    extern __shared__ char smc[];
    uint32_t sbase = smem_u32(smc);
    const int t   = threadIdx.x;
    const int wid = t >> 5;
    const int l   = t & 31;

    const int half = blockIdx.x >= 152;
    const int cta  = blockIdx.x - half * 152;
    const int d_base = half * 64;

    const int per = O_NT / 152;            // 20
    const int rem = O_NT % 152;            // 32
    int start = cta * per + (cta < rem ? cta : rem);
    int cnt = per + (cta < rem ? 1 : 0);

    // ---- stage B half once + first A tile (group 0) ----
    for (int i = t; i < 64 * 48; i += 256) {
        int d = i / 48, c4 = i - d * 48;
        cp_async16(sbase + OMS_B + d * 784 + c4 * 16,
                   g_twB + (d_base + d) * 192 + c4 * 4);
    }
    {
        int tau = start;
        int bb = tau >> 6, w0 = (tau & 63) * 128;
        const float* hb = g_h + (size_t)bb * Wn * Fc;
        for (int i = t; i < 130 * 16; i += 256) {
            int j = i >> 4, c4 = i & 15;
            int gw = (w0 - 1 + j + Wn) & (Wn - 1);
            cp_async16(sbase + OMS_A + j * 272 + c4 * 16, hb + (size_t)gw * Fc + c4 * 4);
        }
    }
    cp_commit();

    const int wg = wid & 3;                // R = wg*32
    const int dg = wid >> 2;               // D = dg*32 (within the 64-half)
    const int R  = wg * 32;
    const int D  = dg * 32;
    const int a_row_in = (l & 7) + ((l >> 3) & 1) * 8;
    const uint32_t a_col = (uint32_t)(l >> 4) * 16;
    const int b_d_in = (l & 7) + (l >> 4) * 8;
    const uint32_t aB = sbase + OMS_B + (uint32_t)(D + b_d_in) * 784
                        + (uint32_t)((l >> 3) & 1) * 16;
    const uint32_t aA = sbase + OMS_A + (uint32_t)(R + a_row_in) * 272 + a_col;
    const int gr  = l >> 2;
    const int gc2 = (l & 3) * 2;

    for (int it = 0; it < cnt; it++) {
        cp_wait0();
        __syncthreads();

        int tau = start + it;
        int bb = tau >> 6, w0 = (tau & 63) * 128;

        float acc[2][4][4];                // [m-tile][n-tile][frag]
        #pragma unroll
        for (int i = 0; i < 2; i++)
            #pragma unroll
            for (int j = 0; j < 4; j++)
                #pragma unroll
                for (int q = 0; q < 4; q++) acc[i][j][q] = 0.f;

        #pragma unroll
        for (int pass = 0; pass < 3; pass++) {
            uint32_t abase = aA + (uint32_t)pass * 272;
            uint32_t bbase = aB + (uint32_t)pass * 256;
            #pragma unroll
            for (int s = 0; s < 8; s++) {
                uint32_t fa0[4], fa1[4], fb0[4], fb1[4];
                ldsm_x4(abase + 32u * s, fa0);
                ldsm_x4(abase + 16u * 272 + 32u * s, fa1);
                ldsm_x4(bbase + 32u * s, fb0);
                ldsm_x4(bbase + 16u * 784 + 32u * s, fb1);
                mma_tf32(acc[0][0], fa0, fb0[0], fb0[1]);
                mma_tf32(acc[0][1], fa0, fb0[2], fb0[3]);
                mma_tf32(acc[0][2], fa0, fb1[0], fb1[1]);
                mma_tf32(acc[0][3], fa0, fb1[2], fb1[3]);
                mma_tf32(acc[1][0], fa1, fb0[0], fb0[1]);
                mma_tf32(acc[1][1], fa1, fb0[2], fb0[3]);
                mma_tf32(acc[1][2], fa1, fb1[0], fb1[1]);
                mma_tf32(acc[1][3], fa1, fb1[2], fb1[3]);
            }
        }

        // write result for this tile
        #pragma unroll
        for (int mt = 0; mt < 2; mt++) {
            #pragma unroll
            for (int ntile = 0; ntile < 4; ntile++) {
                const float* c = acc[mt][ntile];
                int w_row = w0 + R + mt * 16 + gr;
                int d_col = d_base + D + ntile * 8 + gc2;
                float* ob = out + ((size_t)bb * Wn + w_row) * Dc + d_col;
                *(float2*)(ob)          = make_float2(c[0], c[1]);
                *(float2*)(ob + 8 * Dc) = make_float2(c[2], c[3]);
            }
        }
        __syncthreads();                   // all warps done reading A buf

        // stage next A tile (single buffer)
        if (it + 1 < cnt) {
            int tau2 = start + it + 1;
            int bb2 = tau2 >> 6, w02 = (tau2 & 63) * 128;
            const float* hb2 = g_h + (size_t)bb2 * Wn * Fc;
            for (int i = t; i < 130 * 16; i += 256) {
                int j = i >> 4, c4 = i & 15;
                int gw = (w02 - 1 + j + Wn) & (Wn - 1);
                cp_async16(sbase + OMS_A + j * 272 + c4 * 16,
                           hb2 + (size_t)gw * Fc + c4 * 4);
            }
            cp_commit();
        }
    }
}

// ---------------------------------------------------------------------------
extern "C" void kernel_launch(void* const* d_in, const int* in_sizes, int n_in,
                              void* d_out, int out_size) {
    const float* x       = (const float*)d_in[0];
    const float* ctx_w   = (const float*)d_in[1];
    const float* ctx_b   = (const float*)d_in[2];
    const float* token_w = (const float*)d_in[3];
    const float* seW_w   = (const float*)d_in[4];
    const float* seW_b   = (const float*)d_in[5];
    float* out = (float*)d_out;

    cudaFuncSetAttribute(h_mma_kernel,
                         cudaFuncAttributeMaxDynamicSharedMemorySize, HM_SMEM);
    cudaFuncSetAttribute(out_mma_kernel,
                         cudaFuncAttributeMaxDynamicSharedMemorySize, OMS_SMEM);

    gram_partial<<<dim3(GRAM_CHUNKS, Bc), 256>>>(x);
    prep_kernel<<<96, 256>>>(ctx_w, token_w, seW_w);
    gram_reduce<<<Bc, 256>>>();
    h_mma_kernel<<<dim3(Wn / 256, Bc), 512, HM_SMEM>>>(ctx_b, seW_b);
    out_mma_kernel<<<304, 256, OMS_SMEM>>>(out);
}

// round 15
// speedup vs baseline: 1.3764x; 1.3202x over previous
#include <cuda_runtime.h>
#include <cuda_fp16.h>
#include <cstddef>
#include <cstdint>

#define Bc 48
#define Wn 8192
#define Fc 64
#define Dc 128
#define GRAM_CHUNKS 32

typedef unsigned long long ull;

// device scratch (no runtime allocation allowed). 16B-aligned.
__device__ __align__(16) float  g_gram_part[Bc * GRAM_CHUNKS * Fc * Fc];
__device__ __align__(16) __half g_gramh[Bc * Fc * Fc];          // fp16 gram
__device__ __align__(16) __half g_hh[(size_t)Bc * Wn * Fc];     // fp16 h
__device__ __align__(16) __half g_xh[(size_t)Bc * Wn * Fc];     // fp16 x
__device__ __align__(16) __half g_cwBh[64 * 192];               // [f][k*64+g]
__device__ __align__(16) __half g_twBh[128 * 192];              // [d][k*64+f]
__device__ __align__(16) __half g_sewh[Wn * Fc];                // fp16 seW

// ---------------------------------------------------------------------------
// packed f32x2 helpers (gram)
// ---------------------------------------------------------------------------
__device__ __forceinline__ ull dup2(float a) {
    ull r;
    asm("mov.b64 %0, {%1, %1};" : "=l"(r) : "r"(__float_as_uint(a)));
    return r;
}
__device__ __forceinline__ void unpack2(ull v, float& a, float& b) {
    unsigned lo, hi;
    asm("mov.b64 {%0, %1}, %2;" : "=r"(lo), "=r"(hi) : "l"(v));
    a = __uint_as_float(lo); b = __uint_as_float(hi);
}
__device__ __forceinline__ ull ffma2(ull a, ull b, ull c) {
    ull d;
    asm("fma.rn.f32x2 %0, %1, %2, %3;" : "=l"(d) : "l"(a), "l"(b), "l"(c));
    return d;
}

// ---------------------------------------------------------------------------
// tensor-core / async helpers (legacy paths — compile under compute_103)
// ---------------------------------------------------------------------------
__device__ __forceinline__ uint32_t smem_u32(const void* p) {
    uint32_t a;
    asm("{ .reg .u64 t; cvta.to.shared.u64 t, %1; cvt.u32.u64 %0, t; }" : "=r"(a) : "l"(p));
    return a;
}
__device__ __forceinline__ void cp_async16(uint32_t saddr, const void* gptr) {
    asm volatile("cp.async.ca.shared.global [%0], [%1], 16;" :: "r"(saddr), "l"(gptr));
}
__device__ __forceinline__ void cp_commit() {
    asm volatile("cp.async.commit_group;");
}
__device__ __forceinline__ void cp_wait1() {
    asm volatile("cp.async.wait_group 1;" ::: "memory");
}
__device__ __forceinline__ void cp_wait0() {
    asm volatile("cp.async.wait_group 0;" ::: "memory");
}
__device__ __forceinline__ void ldsm_x4(uint32_t addr, uint32_t* r) {
    asm volatile("ldmatrix.sync.aligned.m8n8.x4.shared.b16 {%0,%1,%2,%3}, [%4];"
                 : "=r"(r[0]), "=r"(r[1]), "=r"(r[2]), "=r"(r[3]) : "r"(addr));
}
// fp16 mma: D(f32) = A(f16,16x16) * B(f16,16x8) + D
__device__ __forceinline__ void mma_f16(float* c, const uint32_t* a,
                                        uint32_t b0, uint32_t b1) {
    asm volatile(
        "mma.sync.aligned.m16n8k16.row.col.f32.f16.f16.f32 "
        "{%0,%1,%2,%3}, {%4,%5,%6,%7}, {%8,%9}, {%0,%1,%2,%3};"
        : "+f"(c[0]), "+f"(c[1]), "+f"(c[2]), "+f"(c[3])
        : "r"(a[0]), "r"(a[1]), "r"(a[2]), "r"(a[3]), "r"(b0), "r"(b1));
}

// ---------------------------------------------------------------------------
// Kernel 0: weight reorders + fp16 conversion
// ---------------------------------------------------------------------------
__global__ void __launch_bounds__(256) prep_kernel(
    const float* __restrict__ ctx_w, const float* __restrict__ token_w,
    const float* __restrict__ seW_w) {
    int tid = blockIdx.x * 256 + threadIdx.x;
    int nt = gridDim.x * 256;
    for (int i = tid; i < 64 * 192; i += nt) {
        int f = i / 192, j = i - f * 192;
        int k = j >> 6, g = j & 63;
        g_cwBh[i] = __float2half_rn(ctx_w[f * 192 + g * 3 + k]);
    }
    for (int i = tid; i < 128 * 192; i += nt) {
        int d = i / 192, j = i - d * 192;
        int k = j >> 6, f = j & 63;
        g_twBh[i] = __float2half_rn(token_w[d * 192 + f * 3 + k]);
    }
    for (int i = tid; i < Wn * Fc / 4; i += nt) {
        float4 v = *((const float4*)seW_w + i);
        __half2 h01 = __floats2half2_rn(v.x, v.y);
        __half2 h23 = __floats2half2_rn(v.z, v.w);
        *((uint2*)g_sewh + i) =
            make_uint2(*(uint32_t*)&h01, *(uint32_t*)&h23);
    }
}

// ---------------------------------------------------------------------------
// Kernel 1: per-chunk partial Gram (fp32 FFMA2) + writes fp16 x to g_xh.
// ---------------------------------------------------------------------------
__global__ void __launch_bounds__(256) gram_partial(const float* __restrict__ x) {
    const int b = blockIdx.y;
    const int chunk = blockIdx.x;
    const int w_base = chunk * (Wn / GRAM_CHUNKS);

    __shared__ float xs[64][68];
    __shared__ float npart[4][64];
    __shared__ float sinv2[64];

    const int t = threadIdx.x;
    const int ti = t >> 4;
    const int tj = t & 15;

    ull acc[4][2];
    #pragma unroll
    for (int a = 0; a < 4; a++) { acc[a][0] = 0ull; acc[a][1] = 0ull; }

    const float* xb = x + (size_t)b * Wn * Fc;
    __half* xhb = g_xh + (size_t)b * Wn * Fc;

    for (int tile = 0; tile < 256; tile += 64) {
        for (int i = t; i < 64 * 16; i += 256) {
            int r = i >> 4, c4 = i & 15;
            size_t gofs = (size_t)(w_base + tile + r) * Fc + c4 * 4;
            float4 v = *(const float4*)(xb + gofs);
            *(float4*)(&xs[r][c4 * 4]) = v;
            __half2 h01 = __floats2half2_rn(v.x, v.y);
            __half2 h23 = __floats2half2_rn(v.z, v.w);
            *(uint2*)(xhb + gofs) = make_uint2(*(uint32_t*)&h01, *(uint32_t*)&h23);
        }
        __syncthreads();
        {
            int q = t >> 6, r = t & 63;
            float s = 0.f;
            #pragma unroll
            for (int c = 0; c < 16; c++) { float v = xs[r][q * 16 + c]; s += v * v; }
            npart[q][r] = s;
        }
        __syncthreads();
        if (t < 64)
            sinv2[t] = 1.0f / (npart[0][t] + npart[1][t] + npart[2][t] + npart[3][t]);
        __syncthreads();

        #pragma unroll 4
        for (int w = 0; w < 64; w++) {
            float s = sinv2[w];
            const ull* row = (const ull*)(&xs[w][0]);
            ull vj0 = row[tj], vj1 = row[tj + 16];
            float vi0 = xs[w][ti] * s,      vi1 = xs[w][ti + 16] * s;
            float vi2 = xs[w][ti + 32] * s, vi3 = xs[w][ti + 48] * s;
            acc[0][0] = ffma2(dup2(vi0), vj0, acc[0][0]);
            acc[0][1] = ffma2(dup2(vi0), vj1, acc[0][1]);
            acc[1][0] = ffma2(dup2(vi1), vj0, acc[1][0]);
            acc[1][1] = ffma2(dup2(vi1), vj1, acc[1][1]);
            acc[2][0] = ffma2(dup2(vi2), vj0, acc[2][0]);
            acc[2][1] = ffma2(dup2(vi2), vj1, acc[2][1]);
            acc[3][0] = ffma2(dup2(vi3), vj0, acc[3][0]);
            acc[3][1] = ffma2(dup2(vi3), vj1, acc[3][1]);
        }
        __syncthreads();
    }

    float* dst = g_gram_part + ((size_t)b * GRAM_CHUNKS + chunk) * (Fc * Fc);
    #pragma unroll
    for (int a = 0; a < 4; a++)
        #pragma unroll
        for (int c = 0; c < 2; c++) {
            float u, v;
            unpack2(acc[a][c], u, v);
            *(float2*)(dst + (ti + 16 * a) * 64 + 2 * (tj + 16 * c)) = make_float2(u, v);
        }
}

__global__ void __launch_bounds__(256) gram_reduce() {
    const int b = blockIdx.x;
    const int t = threadIdx.x;
    for (int i = t; i < Fc * Fc; i += 256) {
        float s = 0.f;
        #pragma unroll
        for (int c = 0; c < GRAM_CHUNKS; c++)
            s += g_gram_part[((size_t)b * GRAM_CHUNKS + c) * (Fc * Fc) + i];
        g_gramh[b * Fc * Fc + i] = __float2half_rn(s);
    }
}

// ---------------------------------------------------------------------------
// Kernel H (mma.sync fp16): 256w x 64f per CTA, 16 warps = 8 wg(32w) x 2 fg(32f).
// A strides 144B (64 fp16 + 16B pad), B_conv stride 400B (192 fp16 + pad).
// ---------------------------------------------------------------------------
#define HM_AX   0                         // 258*144 = 37152
#define HM_AS   37152                     // 256*144 = 36864
#define HM_BC   74016                     // 64*400  = 25600
#define HM_BG   99616                     // 64*144  = 9216
#define HM_SMEM 108832

__global__ void __launch_bounds__(512, 1) h_mma_kernel(
    const float* __restrict__ ctx_b,
    const float* __restrict__ seW_b)
{
    extern __shared__ char smc[];
    uint32_t sbase = smem_u32(smc);
    const int t   = threadIdx.x;
    const int wid = t >> 5;
    const int l   = t & 31;
    const int b   = blockIdx.y;
    const int w0  = blockIdx.x * 256;

    const __half* xhb = g_xh + (size_t)b * Wn * Fc;

    // ---- staging (one cp.async group) ----
    for (int i = t; i < 64 * 24; i += 512) {             // BC: 24 chunks/row
        int f = i / 24, c = i - f * 24;
        cp_async16(sbase + HM_BC + f * 400 + c * 16, g_cwBh + f * 192 + c * 8);
    }
    for (int i = t; i < 64 * 8; i += 512) {              // BG: 8 chunks/row
        int f = i >> 3, c = i & 7;
        cp_async16(sbase + HM_BG + f * 144 + c * 16, g_gramh + b * 4096 + f * 64 + c * 8);
    }
    for (int i = t; i < 256 * 8; i += 512) {             // AS
        int r = i >> 3, c = i & 7;
        cp_async16(sbase + HM_AS + r * 144 + c * 16,
                   g_sewh + (size_t)(w0 + r) * Fc + c * 8);
    }
    for (int i = t; i < 258 * 8; i += 512) {             // AX
        int j = i >> 3, c = i & 7;
        int gr = w0 - 1 + j;
        if (gr >= 0 && gr < Wn)
            cp_async16(sbase + HM_AX + j * 144 + c * 16, xhb + (size_t)gr * Fc + c * 8);
        else
            *(uint4*)(smc + HM_AX + j * 144 + c * 16) = make_uint4(0, 0, 0, 0);
    }
    cp_commit();

    const int fg = wid & 1;                // f0 = fg*32
    const int wg = wid >> 1;               // R = wg*32
    const int R  = wg * 32;
    const int f0 = fg * 32;

    const int rl = l & 15;
    const uint32_t ch = (uint32_t)(l >> 4) * 16;
    uint32_t aAX = sbase + HM_AX + (uint32_t)(R + rl) * 144 + ch;
    uint32_t aAS = sbase + HM_AS + (uint32_t)(R + rl) * 144 + ch;
    uint32_t aBC = sbase + HM_BC + (uint32_t)(f0 + rl) * 400 + ch;
    uint32_t aBG = sbase + HM_BG + (uint32_t)(f0 + rl) * 144 + ch;

    const int gr  = l >> 2;
    const int gc2 = (l & 3) * 2;

    float acc[2][4][4];                    // [m-tile][n-tile][frag]
    #pragma unroll
    for (int i = 0; i < 2; i++)
        #pragma unroll
        for (int j = 0; j < 4; j++)
            #pragma unroll
            for (int q = 0; q < 4; q++) acc[i][j][q] = 0.f;

    cp_wait0();
    __syncthreads();

    // ---- SE GEMM: K=64 -> 4 k16-steps ----
    #pragma unroll
    for (int s = 0; s < 4; s++) {
        uint32_t fa0[4], fa1[4], fb0[4], fb1[4];
        ldsm_x4(aAS + 32u * s, fa0);
        ldsm_x4(aAS + 16u * 144 + 32u * s, fa1);
        ldsm_x4(aBG + 32u * s, fb0);
        ldsm_x4(aBG + 16u * 144 + 32u * s, fb1);
        mma_f16(acc[0][0], fa0, fb0[0], fb0[2]);
        mma_f16(acc[0][1], fa0, fb0[1], fb0[3]);
        mma_f16(acc[0][2], fa0, fb1[0], fb1[2]);
        mma_f16(acc[0][3], fa0, fb1[1], fb1[3]);
        mma_f16(acc[1][0], fa1, fb0[0], fb0[2]);
        mma_f16(acc[1][1], fa1, fb0[1], fb0[3]);
        mma_f16(acc[1][2], fa1, fb1[0], fb1[2]);
        mma_f16(acc[1][3], fa1, fb1[1], fb1[3]);
    }

    // ---- transform in place: acc = relu(acc + seb) + ctx_b ----
    {
        int row0 = w0 + R + gr;
        float seb[4];
        seb[0] = __ldg(seW_b + row0);
        seb[1] = __ldg(seW_b + row0 + 8);
        seb[2] = __ldg(seW_b + row0 + 16);
        seb[3] = __ldg(seW_b + row0 + 24);
        #pragma unroll
        for (int mt = 0; mt < 2; mt++) {
            float s0 = seb[mt * 2], s1 = seb[mt * 2 + 1];
            #pragma unroll
            for (int ntile = 0; ntile < 4; ntile++) {
                int col = f0 + ntile * 8 + gc2;
                float c0 = __ldg(ctx_b + col), c1 = __ldg(ctx_b + col + 1);
                float* a = acc[mt][ntile];
                a[0] = fmaxf(a[0] + s0, 0.f) + c0;
                a[1] = fmaxf(a[1] + s0, 0.f) + c1;
                a[2] = fmaxf(a[2] + s1, 0.f) + c0;
                a[3] = fmaxf(a[3] + s1, 0.f) + c1;
            }
        }
    }

    // ---- conv GEMM: 3 passes (A row shift) x 4 k16-steps ----
    #pragma unroll
    for (int pass = 0; pass < 3; pass++) {
        uint32_t abase = aAX + (uint32_t)pass * 144;
        uint32_t bbase = aBC + (uint32_t)pass * 128;
        #pragma unroll
        for (int s = 0; s < 4; s++) {
            uint32_t fa0[4], fa1[4], fb0[4], fb1[4];
            ldsm_x4(abase + 32u * s, fa0);
            ldsm_x4(abase + 16u * 144 + 32u * s, fa1);
            ldsm_x4(bbase + 32u * s, fb0);
            ldsm_x4(bbase + 16u * 400 + 32u * s, fb1);
            mma_f16(acc[0][0], fa0, fb0[0], fb0[2]);
            mma_f16(acc[0][1], fa0, fb0[1], fb0[3]);
            mma_f16(acc[0][2], fa0, fb1[0], fb1[2]);
            mma_f16(acc[0][3], fa0, fb1[1], fb1[3]);
            mma_f16(acc[1][0], fa1, fb0[0], fb0[2]);
            mma_f16(acc[1][1], fa1, fb0[1], fb0[3]);
            mma_f16(acc[1][2], fa1, fb1[0], fb1[2]);
            mma_f16(acc[1][3], fa1, fb1[1], fb1[3]);
        }
    }

    // ---- store h (fp16) ----
    #pragma unroll
    for (int mt = 0; mt < 2; mt++) {
        int row0 = w0 + R + mt * 16 + gr;
        #pragma unroll
        for (int ntile = 0; ntile < 4; ntile++) {
            const float* a = acc[mt][ntile];
            __half* h0 = g_hh + ((size_t)b * Wn + row0) * Fc + f0 + ntile * 8 + gc2;
            __half2 p0 = __floats2half2_rn(a[0], a[1]);
            __half2 p1 = __floats2half2_rn(a[2], a[3]);
            *(__half2*)(h0) = p0;
            *(__half2*)(h0 + 8 * Fc) = p1;
        }
    }
}

// ---------------------------------------------------------------------------
// Kernel O (persistent, mma.sync fp16, d-split, 2 CTAs/SM, double-buffered A):
// grid = 304; CTAs [0,152) -> d 0..63, [152,304) -> d 64..127.
// 256 threads = 8 warps (4 wg(32w) x 2 dg(32d)).
// ---------------------------------------------------------------------------
#define OMS_B    0                        // 64*400 = 25600
#define OMS_A0   25600                    // 130*144 = 18720
#define OMS_A1   44320
#define OMS_SMEM 63040
#define O_NT     3072

__global__ void __launch_bounds__(256, 2) out_mma_kernel(float* __restrict__ out)
{
    extern __shared__ char smc[];
    uint32_t sbase = smem_u32(smc);
    const int t   = threadIdx.x;
    const int wid = t >> 5;
    const int l   = t & 31;

    const uint32_t Ao[2] = {OMS_A0, OMS_A1};

    const int half = blockIdx.x >= 152;
    const int cta  = blockIdx.x - half * 152;
    const int d_base = half * 64;

    const int per = O_NT / 152;            // 20
    const int rem = O_NT % 152;            // 32
    int start = cta * per + (cta < rem ? cta : rem);
    int cnt = per + (cta < rem ? 1 : 0);

    // ---- stage B half once + first A tile (group 0) ----
    for (int i = t; i < 64 * 24; i += 256) {
        int d = i / 24, c = i - d * 24;
        cp_async16(sbase + OMS_B + d * 400 + c * 16,
                   g_twBh + (d_base + d) * 192 + c * 8);
    }
    {
        int tau = start;
        int bb = tau >> 6, w0 = (tau & 63) * 128;
        const __half* hb = g_hh + (size_t)bb * Wn * Fc;
        for (int i = t; i < 130 * 8; i += 256) {
            int j = i >> 3, c = i & 7;
            int gw = (w0 - 1 + j + Wn) & (Wn - 1);
            cp_async16(sbase + OMS_A0 + j * 144 + c * 16, hb + (size_t)gw * Fc + c * 8);
        }
    }
    cp_commit();

    const int wg = wid & 3;                // R = wg*32
    const int dg = wid >> 2;               // D = dg*32
    const int R  = wg * 32;
    const int D  = dg * 32;
    const int rl = l & 15;
    const uint32_t ch = (uint32_t)(l >> 4) * 16;
    const uint32_t aB = sbase + OMS_B + (uint32_t)(D + rl) * 400 + ch;
    const int gr  = l >> 2;
    const int gc2 = (l & 3) * 2;

    for (int it = 0; it < cnt; it++) {
        int buf = it & 1;
        if (it + 1 < cnt) {
            // prefetch next A into other buffer, then wait for current
            int tau2 = start + it + 1;
            int bb2 = tau2 >> 6, w02 = (tau2 & 63) * 128;
            const __half* hb2 = g_hh + (size_t)bb2 * Wn * Fc;
            int nb = buf ^ 1;
            for (int i = t; i < 130 * 8; i += 256) {
                int j = i >> 3, c = i & 7;
                int gw = (w02 - 1 + j + Wn) & (Wn - 1);
                cp_async16(sbase + Ao[nb] + j * 144 + c * 16,
                           hb2 + (size_t)gw * Fc + c * 8);
            }
            cp_commit();
            cp_wait1();
        } else {
            cp_wait0();
        }
        __syncthreads();

        int tau = start + it;
        int bb = tau >> 6, w0 = (tau & 63) * 128;
        uint32_t aA = sbase + Ao[buf] + (uint32_t)(R + rl) * 144 + ch;

        float acc[2][4][4];                // [m-tile][n-tile][frag]
        #pragma unroll
        for (int i = 0; i < 2; i++)
            #pragma unroll
            for (int j = 0; j < 4; j++)
                #pragma unroll
                for (int q = 0; q < 4; q++) acc[i][j][q] = 0.f;

        #pragma unroll
        for (int pass = 0; pass < 3; pass++) {
            uint32_t abase = aA + (uint32_t)pass * 144;
            uint32_t bbase = aB + (uint32_t)pass * 128;
            #pragma unroll
            for (int s = 0; s < 4; s++) {
                uint32_t fa0[4], fa1[4], fb0[4], fb1[4];
                ldsm_x4(abase + 32u * s, fa0);
                ldsm_x4(abase + 16u * 144 + 32u * s, fa1);
                ldsm_x4(bbase + 32u * s, fb0);
                ldsm_x4(bbase + 16u * 400 + 32u * s, fb1);
                mma_f16(acc[0][0], fa0, fb0[0], fb0[2]);
                mma_f16(acc[0][1], fa0, fb0[1], fb0[3]);
                mma_f16(acc[0][2], fa0, fb1[0], fb1[2]);
                mma_f16(acc[0][3], fa0, fb1[1], fb1[3]);
                mma_f16(acc[1][0], fa1, fb0[0], fb0[2]);
                mma_f16(acc[1][1], fa1, fb0[1], fb0[3]);
                mma_f16(acc[1][2], fa1, fb1[0], fb1[2]);
                mma_f16(acc[1][3], fa1, fb1[1], fb1[3]);
            }
        }

        #pragma unroll
        for (int mt = 0; mt < 2; mt++) {
            #pragma unroll
            for (int ntile = 0; ntile < 4; ntile++) {
                const float* c = acc[mt][ntile];
                int w_row = w0 + R + mt * 16 + gr;
                int d_col = d_base + D + ntile * 8 + gc2;
                float* ob = out + ((size_t)bb * Wn + w_row) * Dc + d_col;
                *(float2*)(ob)          = make_float2(c[0], c[1]);
                *(float2*)(ob + 8 * Dc) = make_float2(c[2], c[3]);
            }
        }
        __syncthreads();
    }
}

// ---------------------------------------------------------------------------
extern "C" void kernel_launch(void* const* d_in, const int* in_sizes, int n_in,
                              void* d_out, int out_size) {
    const float* x       = (const float*)d_in[0];
    const float* ctx_w   = (const float*)d_in[1];
    const float* ctx_b   = (const float*)d_in[2];
    const float* token_w = (const float*)d_in[3];
    const float* seW_w   = (const float*)d_in[4];
    const float* seW_b   = (const float*)d_in[5];
    float* out = (float*)d_out;

    cudaFuncSetAttribute(h_mma_kernel,
                         cudaFuncAttributeMaxDynamicSharedMemorySize, HM_SMEM);
    cudaFuncSetAttribute(out_mma_kernel,
                         cudaFuncAttributeMaxDynamicSharedMemorySize, OMS_SMEM);

    gram_partial<<<dim3(GRAM_CHUNKS, Bc), 256>>>(x);
    prep_kernel<<<96, 256>>>(ctx_w, token_w, seW_w);
    gram_reduce<<<Bc, 256>>>();
    h_mma_kernel<<<dim3(Wn / 256, Bc), 512, HM_SMEM>>>(ctx_b, seW_b);
    out_mma_kernel<<<304, 256, OMS_SMEM>>>(out);
}

// round 16
// speedup vs baseline: 1.8137x; 1.3178x over previous
#include <cuda_runtime.h>
#include <cuda_fp16.h>
#include <cstddef>
#include <cstdint>

#define Bc 48
#define Wn 8192
#define Fc 64
#define Dc 128
#define GRAM_CHUNKS 32

typedef unsigned long long ull;

// device scratch (no runtime allocation allowed). 16B-aligned.
__device__ __align__(16) float  g_gram_part[Bc * GRAM_CHUNKS * Fc * Fc];
__device__ __align__(16) __half g_gramh[Bc * Fc * Fc];          // fp16 gram
__device__ __align__(16) __half g_hh[(size_t)Bc * Wn * Fc];     // fp16 h
__device__ __align__(16) __half g_xh[(size_t)Bc * Wn * Fc];     // fp16 x
__device__ __align__(16) __half g_cwBh[64 * 192];               // [f][k*64+g]
__device__ __align__(16) __half g_twBh[128 * 192];              // [d][k*64+f]
__device__ __align__(16) __half g_sewh[Wn * Fc];                // fp16 seW

// ---------------------------------------------------------------------------
// tensor-core / async helpers (legacy paths — compile under compute_103)
// ---------------------------------------------------------------------------
__device__ __forceinline__ uint32_t smem_u32(const void* p) {
    uint32_t a;
    asm("{ .reg .u64 t; cvta.to.shared.u64 t, %1; cvt.u32.u64 %0, t; }" : "=r"(a) : "l"(p));
    return a;
}
__device__ __forceinline__ void cp_async16(uint32_t saddr, const void* gptr) {
    asm volatile("cp.async.ca.shared.global [%0], [%1], 16;" :: "r"(saddr), "l"(gptr));
}
__device__ __forceinline__ void cp_commit() {
    asm volatile("cp.async.commit_group;");
}
__device__ __forceinline__ void cp_wait1() {
    asm volatile("cp.async.wait_group 1;" ::: "memory");
}
__device__ __forceinline__ void cp_wait0() {
    asm volatile("cp.async.wait_group 0;" ::: "memory");
}
__device__ __forceinline__ void ldsm_x4(uint32_t addr, uint32_t* r) {
    asm volatile("ldmatrix.sync.aligned.m8n8.x4.shared.b16 {%0,%1,%2,%3}, [%4];"
                 : "=r"(r[0]), "=r"(r[1]), "=r"(r[2]), "=r"(r[3]) : "r"(addr));
}
// fp16 mma: D(f32) = A(f16,16x16) * B(f16,16x8)^T-ish (row.col) + D
__device__ __forceinline__ void mma_f16(float* c, const uint32_t* a,
                                        uint32_t b0, uint32_t b1) {
    asm volatile(
        "mma.sync.aligned.m16n8k16.row.col.f32.f16.f16.f32 "
        "{%0,%1,%2,%3}, {%4,%5,%6,%7}, {%8,%9}, {%0,%1,%2,%3};"
        : "+f"(c[0]), "+f"(c[1]), "+f"(c[2]), "+f"(c[3])
        : "r"(a[0]), "r"(a[1]), "r"(a[2]), "r"(a[3]), "r"(b0), "r"(b1));
}

// ---------------------------------------------------------------------------
// Kernel 0: weight reorders + fp16 conversion
// ---------------------------------------------------------------------------
__global__ void __launch_bounds__(256) prep_kernel(
    const float* __restrict__ ctx_w, const float* __restrict__ token_w,
    const float* __restrict__ seW_w) {
    int tid = blockIdx.x * 256 + threadIdx.x;
    int nt = gridDim.x * 256;
    for (int i = tid; i < 64 * 192; i += nt) {
        int f = i / 192, j = i - f * 192;
        int k = j >> 6, g = j & 63;
        g_cwBh[i] = __float2half_rn(ctx_w[f * 192 + g * 3 + k]);
    }
    for (int i = tid; i < 128 * 192; i += nt) {
        int d = i / 192, j = i - d * 192;
        int k = j >> 6, f = j & 63;
        g_twBh[i] = __float2half_rn(token_w[d * 192 + f * 3 + k]);
    }
    for (int i = tid; i < Wn * Fc / 4; i += nt) {
        float4 v = *((const float4*)seW_w + i);
        __half2 h01 = __floats2half2_rn(v.x, v.y);
        __half2 h23 = __floats2half2_rn(v.z, v.w);
        *((uint2*)g_sewh + i) =
            make_uint2(*(uint32_t*)&h01, *(uint32_t*)&h23);
    }
}

// ---------------------------------------------------------------------------
// Kernel 1 (mma.sync fp16): per-chunk partial Gram + writes fp16 x to g_xh.
// gram[i][j] = sum_w (x[w,i]*sinv2_w) * x[w,j]
// 128 threads = 4 warps, each computes a 32i x 32j quadrant, accumulating
// over 4 sub-tiles of 64 w-rows. Transposed fp16 tiles xnT (scaled) / xT.
// ---------------------------------------------------------------------------
__global__ void __launch_bounds__(128) gram_mma(const float* __restrict__ x) {
    __shared__ float xs[64][68];
    __shared__ float npart[2][64];
    __shared__ float sinv2[64];
    __shared__ __align__(16) __half xnT[64 * 72];   // [f][w], stride 72 halfs
    __shared__ __align__(16) __half xT[64 * 72];

    const int b = blockIdx.y;
    const int chunk = blockIdx.x;
    const int w_base = chunk * (Wn / GRAM_CHUNKS);  // 256 rows per chunk

    const int t   = threadIdx.x;
    const int wid = t >> 5;
    const int l   = t & 31;

    const float* xb = x + (size_t)b * Wn * Fc;
    __half* xhb = g_xh + (size_t)b * Wn * Fc;

    // warp quadrant + fragment addressing (same pattern as h kernel)
    const int I = (wid & 1) * 32;
    const int J = (wid >> 1) * 32;
    const int rl = l & 15;
    const uint32_t ch = (uint32_t)(l >> 4) * 16;
    const uint32_t aA = smem_u32(xnT) + (uint32_t)(I + rl) * 144 + ch;
    const uint32_t aB = smem_u32(xT)  + (uint32_t)(J + rl) * 144 + ch;

    float acc[2][4][4];
    #pragma unroll
    for (int i = 0; i < 2; i++)
        #pragma unroll
        for (int j = 0; j < 4; j++)
            #pragma unroll
            for (int q = 0; q < 4; q++) acc[i][j][q] = 0.f;

    for (int tile = 0; tile < 4; tile++) {
        const int tb = w_base + tile * 64;
        // ---- load 64 rows fp32 (+ side-write fp16 x) ----
        for (int i = t; i < 64 * 16; i += 128) {
            int r = i >> 4, c4 = i & 15;
            size_t gofs = (size_t)(tb + r) * Fc + c4 * 4;
            float4 v = *(const float4*)(xb + gofs);
            *(float4*)(&xs[r][c4 * 4]) = v;
            __half2 h01 = __floats2half2_rn(v.x, v.y);
            __half2 h23 = __floats2half2_rn(v.z, v.w);
            *(uint2*)(xhb + gofs) = make_uint2(*(uint32_t*)&h01, *(uint32_t*)&h23);
        }
        __syncthreads();
        // ---- parallel norm: 2 threads per row ----
        {
            int q = t >> 6, r = t & 63;
            float s = 0.f;
            #pragma unroll
            for (int c = 0; c < 32; c++) { float v = xs[r][q * 32 + c]; s += v * v; }
            npart[q][r] = s;
        }
        __syncthreads();
        if (t < 64) sinv2[t] = 1.0f / (npart[0][t] + npart[1][t]);
        __syncthreads();
        // ---- convert-transpose: thread = (f = t>>1, wh = t&1), half2 stores ----
        {
            int f = t >> 1, wh = t & 1;
            int wlo = wh * 32;
            __half* dn = xnT + f * 72 + wlo;
            __half* du = xT  + f * 72 + wlo;
            #pragma unroll
            for (int w2 = 0; w2 < 16; w2++) {
                int w = 2 * w2;
                float v0 = xs[wlo + w][f],     s0 = sinv2[wlo + w];
                float v1 = xs[wlo + w + 1][f], s1 = sinv2[wlo + w + 1];
                *(__half2*)(dn + w) = __floats2half2_rn(v0 * s0, v1 * s1);
                *(__half2*)(du + w) = __floats2half2_rn(v0, v1);
            }
        }
        __syncthreads();
        // ---- mma: K=64 -> 4 k16-steps ----
        #pragma unroll
        for (int s = 0; s < 4; s++) {
            uint32_t fa0[4], fa1[4], fb0[4], fb1[4];
            ldsm_x4(aA + 32u * s, fa0);
            ldsm_x4(aA + 16u * 144 + 32u * s, fa1);
            ldsm_x4(aB + 32u * s, fb0);
            ldsm_x4(aB + 16u * 144 + 32u * s, fb1);
            mma_f16(acc[0][0], fa0, fb0[0], fb0[2]);
            mma_f16(acc[0][1], fa0, fb0[1], fb0[3]);
            mma_f16(acc[0][2], fa0, fb1[0], fb1[2]);
            mma_f16(acc[0][3], fa0, fb1[1], fb1[3]);
            mma_f16(acc[1][0], fa1, fb0[0], fb0[2]);
            mma_f16(acc[1][1], fa1, fb0[1], fb0[3]);
            mma_f16(acc[1][2], fa1, fb1[0], fb1[2]);
            mma_f16(acc[1][3], fa1, fb1[1], fb1[3]);
        }
        __syncthreads();
    }

    // ---- write 64x64 partial ----
    float* dst = g_gram_part + ((size_t)b * GRAM_CHUNKS + chunk) * (Fc * Fc);
    const int gr  = l >> 2;
    const int gc2 = (l & 3) * 2;
    #pragma unroll
    for (int mt = 0; mt < 2; mt++) {
        #pragma unroll
        for (int ntile = 0; ntile < 4; ntile++) {
            const float* c = acc[mt][ntile];
            int row = I + mt * 16 + gr;
            int col = J + ntile * 8 + gc2;
            *(float2*)(dst + row * 64 + col)       = make_float2(c[0], c[1]);
            *(float2*)(dst + (row + 8) * 64 + col) = make_float2(c[2], c[3]);
        }
    }
}

__global__ void __launch_bounds__(256) gram_reduce() {
    const int b = blockIdx.x;
    const int t = threadIdx.x;
    for (int i = t; i < Fc * Fc; i += 256) {
        float s = 0.f;
        #pragma unroll
        for (int c = 0; c < GRAM_CHUNKS; c++)
            s += g_gram_part[((size_t)b * GRAM_CHUNKS + c) * (Fc * Fc) + i];
        g_gramh[b * Fc * Fc + i] = __float2half_rn(s);
    }
}

// ---------------------------------------------------------------------------
// Kernel H (mma.sync fp16): R15 winner, unchanged.
// 256w x 64f per CTA, 16 warps = 8 wg(32w) x 2 fg(32f).
// ---------------------------------------------------------------------------
#define HM_AX   0                         // 258*144 = 37152
#define HM_AS   37152                     // 256*144 = 36864
#define HM_BC   74016                     // 64*400  = 25600
#define HM_BG   99616                     // 64*144  = 9216
#define HM_SMEM 108832

__global__ void __launch_bounds__(512, 1) h_mma_kernel(
    const float* __restrict__ ctx_b,
    const float* __restrict__ seW_b)
{
    extern __shared__ char smc[];
    uint32_t sbase = smem_u32(smc);
    const int t   = threadIdx.x;
    const int wid = t >> 5;
    const int l   = t & 31;
    const int b   = blockIdx.y;
    const int w0  = blockIdx.x * 256;

    const __half* xhb = g_xh + (size_t)b * Wn * Fc;

    for (int i = t; i < 64 * 24; i += 512) {
        int f = i / 24, c = i - f * 24;
        cp_async16(sbase + HM_BC + f * 400 + c * 16, g_cwBh + f * 192 + c * 8);
    }
    for (int i = t; i < 64 * 8; i += 512) {
        int f = i >> 3, c = i & 7;
        cp_async16(sbase + HM_BG + f * 144 + c * 16, g_gramh + b * 4096 + f * 64 + c * 8);
    }
    for (int i = t; i < 256 * 8; i += 512) {
        int r = i >> 3, c = i & 7;
        cp_async16(sbase + HM_AS + r * 144 + c * 16,
                   g_sewh + (size_t)(w0 + r) * Fc + c * 8);
    }
    for (int i = t; i < 258 * 8; i += 512) {
        int j = i >> 3, c = i & 7;
        int gr = w0 - 1 + j;
        if (gr >= 0 && gr < Wn)
            cp_async16(sbase + HM_AX + j * 144 + c * 16, xhb + (size_t)gr * Fc + c * 8);
        else
            *(uint4*)(smc + HM_AX + j * 144 + c * 16) = make_uint4(0, 0, 0, 0);
    }
    cp_commit();

    const int fg = wid & 1;
    const int wg = wid >> 1;
    const int R  = wg * 32;
    const int f0 = fg * 32;

    const int rl = l & 15;
    const uint32_t ch = (uint32_t)(l >> 4) * 16;
    uint32_t aAX = sbase + HM_AX + (uint32_t)(R + rl) * 144 + ch;
    uint32_t aAS = sbase + HM_AS + (uint32_t)(R + rl) * 144 + ch;
    uint32_t aBC = sbase + HM_BC + (uint32_t)(f0 + rl) * 400 + ch;
    uint32_t aBG = sbase + HM_BG + (uint32_t)(f0 + rl) * 144 + ch;

    const int gr  = l >> 2;
    const int gc2 = (l & 3) * 2;

    float acc[2][4][4];
    #pragma unroll
    for (int i = 0; i < 2; i++)
        #pragma unroll
        for (int j = 0; j < 4; j++)
            #pragma unroll
            for (int q = 0; q < 4; q++) acc[i][j][q] = 0.f;

    cp_wait0();
    __syncthreads();

    // SE GEMM: K=64 -> 4 k16-steps
    #pragma unroll
    for (int s = 0; s < 4; s++) {
        uint32_t fa0[4], fa1[4], fb0[4], fb1[4];
        ldsm_x4(aAS + 32u * s, fa0);
        ldsm_x4(aAS + 16u * 144 + 32u * s, fa1);
        ldsm_x4(aBG + 32u * s, fb0);
        ldsm_x4(aBG + 16u * 144 + 32u * s, fb1);
        mma_f16(acc[0][0], fa0, fb0[0], fb0[2]);
        mma_f16(acc[0][1], fa0, fb0[1], fb0[3]);
        mma_f16(acc[0][2], fa0, fb1[0], fb1[2]);
        mma_f16(acc[0][3], fa0, fb1[1], fb1[3]);
        mma_f16(acc[1][0], fa1, fb0[0], fb0[2]);
        mma_f16(acc[1][1], fa1, fb0[1], fb0[3]);
        mma_f16(acc[1][2], fa1, fb1[0], fb1[2]);
        mma_f16(acc[1][3], fa1, fb1[1], fb1[3]);
    }

    // transform in place: acc = relu(acc + seb) + ctx_b
    {
        int row0 = w0 + R + gr;
        float seb[4];
        seb[0] = __ldg(seW_b + row0);
        seb[1] = __ldg(seW_b + row0 + 8);
        seb[2] = __ldg(seW_b + row0 + 16);
        seb[3] = __ldg(seW_b + row0 + 24);
        #pragma unroll
        for (int mt = 0; mt < 2; mt++) {
            float s0 = seb[mt * 2], s1 = seb[mt * 2 + 1];
            #pragma unroll
            for (int ntile = 0; ntile < 4; ntile++) {
                int col = f0 + ntile * 8 + gc2;
                float c0 = __ldg(ctx_b + col), c1 = __ldg(ctx_b + col + 1);
                float* a = acc[mt][ntile];
                a[0] = fmaxf(a[0] + s0, 0.f) + c0;
                a[1] = fmaxf(a[1] + s0, 0.f) + c1;
                a[2] = fmaxf(a[2] + s1, 0.f) + c0;
                a[3] = fmaxf(a[3] + s1, 0.f) + c1;
            }
        }
    }

    // conv GEMM: 3 passes (A row shift) x 4 k16-steps
    #pragma unroll
    for (int pass = 0; pass < 3; pass++) {
        uint32_t abase = aAX + (uint32_t)pass * 144;
        uint32_t bbase = aBC + (uint32_t)pass * 128;
        #pragma unroll
        for (int s = 0; s < 4; s++) {
            uint32_t fa0[4], fa1[4], fb0[4], fb1[4];
            ldsm_x4(abase + 32u * s, fa0);
            ldsm_x4(abase + 16u * 144 + 32u * s, fa1);
            ldsm_x4(bbase + 32u * s, fb0);
            ldsm_x4(bbase + 16u * 400 + 32u * s, fb1);
            mma_f16(acc[0][0], fa0, fb0[0], fb0[2]);
            mma_f16(acc[0][1], fa0, fb0[1], fb0[3]);
            mma_f16(acc[0][2], fa0, fb1[0], fb1[2]);
            mma_f16(acc[0][3], fa0, fb1[1], fb1[3]);
            mma_f16(acc[1][0], fa1, fb0[0], fb0[2]);
            mma_f16(acc[1][1], fa1, fb0[1], fb0[3]);
            mma_f16(acc[1][2], fa1, fb1[0], fb1[2]);
            mma_f16(acc[1][3], fa1, fb1[1], fb1[3]);
        }
    }

    // store h (fp16)
    #pragma unroll
    for (int mt = 0; mt < 2; mt++) {
        int row0 = w0 + R + mt * 16 + gr;
        #pragma unroll
        for (int ntile = 0; ntile < 4; ntile++) {
            const float* a = acc[mt][ntile];
            __half* h0 = g_hh + ((size_t)b * Wn + row0) * Fc + f0 + ntile * 8 + gc2;
            __half2 p0 = __floats2half2_rn(a[0], a[1]);
            __half2 p1 = __floats2half2_rn(a[2], a[3]);
            *(__half2*)(h0) = p0;
            *(__half2*)(h0 + 8 * Fc) = p1;
        }
    }
}

// ---------------------------------------------------------------------------
// Kernel O (persistent, mma.sync fp16, d-split, 2 CTAs/SM, double-buffered A):
// R15 winner, unchanged.
// ---------------------------------------------------------------------------
#define OMS_B    0                        // 64*400 = 25600
#define OMS_A0   25600                    // 130*144 = 18720
#define OMS_A1   44320
#define OMS_SMEM 63040
#define O_NT     3072

__global__ void __launch_bounds__(256, 2) out_mma_kernel(float* __restrict__ out)
{
    extern __shared__ char smc[];
    uint32_t sbase = smem_u32(smc);
    const int t   = threadIdx.x;
    const int wid = t >> 5;
    const int l   = t & 31;

    const uint32_t Ao[2] = {OMS_A0, OMS_A1};

    const int half = blockIdx.x >= 152;
    const int cta  = blockIdx.x - half * 152;
    const int d_base = half * 64;

    const int per = O_NT / 152;
    const int rem = O_NT % 152;
    int start = cta * per + (cta < rem ? cta : rem);
    int cnt = per + (cta < rem ? 1 : 0);

    for (int i = t; i < 64 * 24; i += 256) {
        int d = i / 24, c = i - d * 24;
        cp_async16(sbase + OMS_B + d * 400 + c * 16,
                   g_twBh + (d_base + d) * 192 + c * 8);
    }
    {
        int tau = start;
        int bb = tau >> 6, w0 = (tau & 63) * 128;
        const __half* hb = g_hh + (size_t)bb * Wn * Fc;
        for (int i = t; i < 130 * 8; i += 256) {
            int j = i >> 3, c = i & 7;
            int gw = (w0 - 1 + j + Wn) & (Wn - 1);
            cp_async16(sbase + OMS_A0 + j * 144 + c * 16, hb + (size_t)gw * Fc + c * 8);
        }
    }
    cp_commit();

    const int wg = wid & 3;
    const int dg = wid >> 2;
    const int R  = wg * 32;
    const int D  = dg * 32;
    const int rl = l & 15;
    const uint32_t ch = (uint32_t)(l >> 4) * 16;
    const uint32_t aB = sbase + OMS_B + (uint32_t)(D + rl) * 400 + ch;
    const int gr  = l >> 2;
    const int gc2 = (l & 3) * 2;

    for (int it = 0; it < cnt; it++) {
        int buf = it & 1;
        if (it + 1 < cnt) {
            int tau2 = start + it + 1;
            int bb2 = tau2 >> 6, w02 = (tau2 & 63) * 128;
            const __half* hb2 = g_hh + (size_t)bb2 * Wn * Fc;
            int nb = buf ^ 1;
            for (int i = t; i < 130 * 8; i += 256) {
                int j = i >> 3, c = i & 7;
                int gw = (w02 - 1 + j + Wn) & (Wn - 1);
                cp_async16(sbase + Ao[nb] + j * 144 + c * 16,
                           hb2 + (size_t)gw * Fc + c * 8);
            }
            cp_commit();
            cp_wait1();
        } else {
            cp_wait0();
        }
        __syncthreads();

        int tau = start + it;
        int bb = tau >> 6, w0 = (tau & 63) * 128;
        uint32_t aA = sbase + Ao[buf] + (uint32_t)(R + rl) * 144 + ch;

        float acc[2][4][4];
        #pragma unroll
        for (int i = 0; i < 2; i++)
            #pragma unroll
            for (int j = 0; j < 4; j++)
                #pragma unroll
                for (int q = 0; q < 4; q++) acc[i][j][q] = 0.f;

        #pragma unroll
        for (int pass = 0; pass < 3; pass++) {
            uint32_t abase = aA + (uint32_t)pass * 144;
            uint32_t bbase = aB + (uint32_t)pass * 128;
            #pragma unroll
            for (int s = 0; s < 4; s++) {
                uint32_t fa0[4], fa1[4], fb0[4], fb1[4];
                ldsm_x4(abase + 32u * s, fa0);
                ldsm_x4(abase + 16u * 144 + 32u * s, fa1);
                ldsm_x4(bbase + 32u * s, fb0);
                ldsm_x4(bbase + 16u * 400 + 32u * s, fb1);
                mma_f16(acc[0][0], fa0, fb0[0], fb0[2]);
                mma_f16(acc[0][1], fa0, fb0[1], fb0[3]);
                mma_f16(acc[0][2], fa0, fb1[0], fb1[2]);
                mma_f16(acc[0][3], fa0, fb1[1], fb1[3]);
                mma_f16(acc[1][0], fa1, fb0[0], fb0[2]);
                mma_f16(acc[1][1], fa1, fb0[1], fb0[3]);
                mma_f16(acc[1][2], fa1, fb1[0], fb1[2]);
                mma_f16(acc[1][3], fa1, fb1[1], fb1[3]);
            }
        }

        #pragma unroll
        for (int mt = 0; mt < 2; mt++) {
            #pragma unroll
            for (int ntile = 0; ntile < 4; ntile++) {
                const float* c = acc[mt][ntile];
                int w_row = w0 + R + mt * 16 + gr;
                int d_col = d_base + D + ntile * 8 + gc2;
                float* ob = out + ((size_t)bb * Wn + w_row) * Dc + d_col;
                *(float2*)(ob)          = make_float2(c[0], c[1]);
                *(float2*)(ob + 8 * Dc) = make_float2(c[2], c[3]);
            }
        }
        __syncthreads();
    }
}

// ---------------------------------------------------------------------------
extern "C" void kernel_launch(void* const* d_in, const int* in_sizes, int n_in,
                              void* d_out, int out_size) {
    const float* x       = (const float*)d_in[0];
    const float* ctx_w   = (const float*)d_in[1];
    const float* ctx_b   = (const float*)d_in[2];
    const float* token_w = (const float*)d_in[3];
    const float* seW_w   = (const float*)d_in[4];
    const float* seW_b   = (const float*)d_in[5];
    float* out = (float*)d_out;

    cudaFuncSetAttribute(h_mma_kernel,
                         cudaFuncAttributeMaxDynamicSharedMemorySize, HM_SMEM);
    cudaFuncSetAttribute(out_mma_kernel,
                         cudaFuncAttributeMaxDynamicSharedMemorySize, OMS_SMEM);

    gram_mma<<<dim3(GRAM_CHUNKS, Bc), 128>>>(x);
    prep_kernel<<<96, 256>>>(ctx_w, token_w, seW_w);
    gram_reduce<<<Bc, 256>>>();
    h_mma_kernel<<<dim3(Wn / 256, Bc), 512, HM_SMEM>>>(ctx_b, seW_b);
    out_mma_kernel<<<304, 256, OMS_SMEM>>>(out);
}

// round 17
// speedup vs baseline: 1.8666x; 1.0292x over previous
#include <cuda_runtime.h>
#include <cuda_fp16.h>
#include <cstddef>
#include <cstdint>

#define Bc 48
#define Wn 8192
#define Fc 64
#define Dc 128
#define GRAM_CHUNKS 32

typedef unsigned long long ull;

// device scratch (no runtime allocation allowed). 16B-aligned.
__device__ __align__(16) float  g_gram_part[Bc * GRAM_CHUNKS * Fc * Fc];
__device__ __align__(16) __half g_gramh[Bc * Fc * Fc];          // fp16 gram
__device__ __align__(16) __half g_hh[(size_t)Bc * Wn * Fc];     // fp16 h
__device__ __align__(16) __half g_xh[(size_t)Bc * Wn * Fc];     // fp16 x
__device__ __align__(16) __half g_cwBh[64 * 192];               // [f][k*64+g]
__device__ __align__(16) __half g_twBh[128 * 192];              // [d][k*64+f]
__device__ __align__(16) __half g_sewh[Wn * Fc];                // fp16 seW

// ---------------------------------------------------------------------------
// tensor-core / async helpers (legacy paths — compile under compute_103)
// ---------------------------------------------------------------------------
__device__ __forceinline__ uint32_t smem_u32(const void* p) {
    uint32_t a;
    asm("{ .reg .u64 t; cvta.to.shared.u64 t, %1; cvt.u32.u64 %0, t; }" : "=r"(a) : "l"(p));
    return a;
}
__device__ __forceinline__ void cp_async16(uint32_t saddr, const void* gptr) {
    asm volatile("cp.async.ca.shared.global [%0], [%1], 16;" :: "r"(saddr), "l"(gptr));
}
__device__ __forceinline__ void cp_commit() {
    asm volatile("cp.async.commit_group;");
}
__device__ __forceinline__ void cp_wait1() {
    asm volatile("cp.async.wait_group 1;" ::: "memory");
}
__device__ __forceinline__ void cp_wait0() {
    asm volatile("cp.async.wait_group 0;" ::: "memory");
}
__device__ __forceinline__ void ldsm_x4(uint32_t addr, uint32_t* r) {
    asm volatile("ldmatrix.sync.aligned.m8n8.x4.shared.b16 {%0,%1,%2,%3}, [%4];"
                 : "=r"(r[0]), "=r"(r[1]), "=r"(r[2]), "=r"(r[3]) : "r"(addr));
}
__device__ __forceinline__ void mma_f16(float* c, const uint32_t* a,
                                        uint32_t b0, uint32_t b1) {
    asm volatile(
        "mma.sync.aligned.m16n8k16.row.col.f32.f16.f16.f32 "
        "{%0,%1,%2,%3}, {%4,%5,%6,%7}, {%8,%9}, {%0,%1,%2,%3};"
        : "+f"(c[0]), "+f"(c[1]), "+f"(c[2]), "+f"(c[3])
        : "r"(a[0]), "r"(a[1]), "r"(a[2]), "r"(a[3]), "r"(b0), "r"(b1));
}

// ---------------------------------------------------------------------------
// Kernel 0: weight reorders + fp16 conversion
// ---------------------------------------------------------------------------
__global__ void __launch_bounds__(256) prep_kernel(
    const float* __restrict__ ctx_w, const float* __restrict__ token_w,
    const float* __restrict__ seW_w) {
    int tid = blockIdx.x * 256 + threadIdx.x;
    int nt = gridDim.x * 256;
    for (int i = tid; i < 64 * 192; i += nt) {
        int f = i / 192, j = i - f * 192;
        int k = j >> 6, g = j & 63;
        g_cwBh[i] = __float2half_rn(ctx_w[f * 192 + g * 3 + k]);
    }
    for (int i = tid; i < 128 * 192; i += nt) {
        int d = i / 192, j = i - d * 192;
        int k = j >> 6, f = j & 63;
        g_twBh[i] = __float2half_rn(token_w[d * 192 + f * 3 + k]);
    }
    for (int i = tid; i < Wn * Fc / 4; i += nt) {
        float4 v = *((const float4*)seW_w + i);
        __half2 h01 = __floats2half2_rn(v.x, v.y);
        __half2 h23 = __floats2half2_rn(v.z, v.w);
        *((uint2*)g_sewh + i) =
            make_uint2(*(uint32_t*)&h01, *(uint32_t*)&h23);
    }
}

// ---------------------------------------------------------------------------
// Kernel 1 (mma.sync fp16): per-chunk partial Gram + writes fp16 x to g_xh.
// (R16 winner, unchanged)
// ---------------------------------------------------------------------------
__global__ void __launch_bounds__(128) gram_mma(const float* __restrict__ x) {
    __shared__ float xs[64][68];
    __shared__ float npart[2][64];
    __shared__ float sinv2[64];
    __shared__ __align__(16) __half xnT[64 * 72];
    __shared__ __align__(16) __half xT[64 * 72];

    const int b = blockIdx.y;
    const int chunk = blockIdx.x;
    const int w_base = chunk * (Wn / GRAM_CHUNKS);

    const int t   = threadIdx.x;
    const int wid = t >> 5;
    const int l   = t & 31;

    const float* xb = x + (size_t)b * Wn * Fc;
    __half* xhb = g_xh + (size_t)b * Wn * Fc;

    const int I = (wid & 1) * 32;
    const int J = (wid >> 1) * 32;
    const int rl = l & 15;
    const uint32_t ch = (uint32_t)(l >> 4) * 16;
    const uint32_t aA = smem_u32(xnT) + (uint32_t)(I + rl) * 144 + ch;
    const uint32_t aB = smem_u32(xT)  + (uint32_t)(J + rl) * 144 + ch;

    float acc[2][4][4];
    #pragma unroll
    for (int i = 0; i < 2; i++)
        #pragma unroll
        for (int j = 0; j < 4; j++)
            #pragma unroll
            for (int q = 0; q < 4; q++) acc[i][j][q] = 0.f;

    for (int tile = 0; tile < 4; tile++) {
        const int tb = w_base + tile * 64;
        for (int i = t; i < 64 * 16; i += 128) {
            int r = i >> 4, c4 = i & 15;
            size_t gofs = (size_t)(tb + r) * Fc + c4 * 4;
            float4 v = *(const float4*)(xb + gofs);
            *(float4*)(&xs[r][c4 * 4]) = v;
            __half2 h01 = __floats2half2_rn(v.x, v.y);
            __half2 h23 = __floats2half2_rn(v.z, v.w);
            *(uint2*)(xhb + gofs) = make_uint2(*(uint32_t*)&h01, *(uint32_t*)&h23);
        }
        __syncthreads();
        {
            int q = t >> 6, r = t & 63;
            float s = 0.f;
            #pragma unroll
            for (int c = 0; c < 32; c++) { float v = xs[r][q * 32 + c]; s += v * v; }
            npart[q][r] = s;
        }
        __syncthreads();
        if (t < 64) sinv2[t] = 1.0f / (npart[0][t] + npart[1][t]);
        __syncthreads();
        {
            int f = t >> 1, wh = t & 1;
            int wlo = wh * 32;
            __half* dn = xnT + f * 72 + wlo;
            __half* du = xT  + f * 72 + wlo;
            #pragma unroll
            for (int w2 = 0; w2 < 16; w2++) {
                int w = 2 * w2;
                float v0 = xs[wlo + w][f],     s0 = sinv2[wlo + w];
                float v1 = xs[wlo + w + 1][f], s1 = sinv2[wlo + w + 1];
                *(__half2*)(dn + w) = __floats2half2_rn(v0 * s0, v1 * s1);
                *(__half2*)(du + w) = __floats2half2_rn(v0, v1);
            }
        }
        __syncthreads();
        #pragma unroll
        for (int s = 0; s < 4; s++) {
            uint32_t fa0[4], fa1[4], fb0[4], fb1[4];
            ldsm_x4(aA + 32u * s, fa0);
            ldsm_x4(aA + 16u * 144 + 32u * s, fa1);
            ldsm_x4(aB + 32u * s, fb0);
            ldsm_x4(aB + 16u * 144 + 32u * s, fb1);
            mma_f16(acc[0][0], fa0, fb0[0], fb0[2]);
            mma_f16(acc[0][1], fa0, fb0[1], fb0[3]);
            mma_f16(acc[0][2], fa0, fb1[0], fb1[2]);
            mma_f16(acc[0][3], fa0, fb1[1], fb1[3]);
            mma_f16(acc[1][0], fa1, fb0[0], fb0[2]);
            mma_f16(acc[1][1], fa1, fb0[1], fb0[3]);
            mma_f16(acc[1][2], fa1, fb1[0], fb1[2]);
            mma_f16(acc[1][3], fa1, fb1[1], fb1[3]);
        }
        __syncthreads();
    }

    float* dst = g_gram_part + ((size_t)b * GRAM_CHUNKS + chunk) * (Fc * Fc);
    const int gr  = l >> 2;
    const int gc2 = (l & 3) * 2;
    #pragma unroll
    for (int mt = 0; mt < 2; mt++) {
        #pragma unroll
        for (int ntile = 0; ntile < 4; ntile++) {
            const float* c = acc[mt][ntile];
            int row = I + mt * 16 + gr;
            int col = J + ntile * 8 + gc2;
            *(float2*)(dst + row * 64 + col)       = make_float2(c[0], c[1]);
            *(float2*)(dst + (row + 8) * 64 + col) = make_float2(c[2], c[3]);
        }
    }
}

__global__ void __launch_bounds__(256) gram_reduce() {
    const int b = blockIdx.x;
    const int t = threadIdx.x;
    for (int i = t; i < Fc * Fc; i += 256) {
        float s = 0.f;
        #pragma unroll
        for (int c = 0; c < GRAM_CHUNKS; c++)
            s += g_gram_part[((size_t)b * GRAM_CHUNKS + c) * (Fc * Fc) + i];
        g_gramh[b * Fc * Fc + i] = __float2half_rn(s);
    }
}

// ---------------------------------------------------------------------------
// Kernel H (persistent, mma.sync fp16): 256w x 64f tiles, double-buffered
// {AX, AS, BG}, BC staged once. 152 CTAs x 512 threads (16 warps, 32w x 32f).
// Per-buffer layout (offsets within buffer):
//   AX 0       (258*144 = 37152)
//   AS 37152   (256*144 = 36864)
//   BG 74016   (64*144  = 9216)   -> buffer size 83232
// ---------------------------------------------------------------------------
#define HP_BC    0                        // 64*400 = 25600
#define HP_B0    25600
#define HP_B1    108832
#define HP_AS_O  37152
#define HP_BG_O  74016
#define HP_SMEM  192064
#define H_NT     1536                     // 256-row tiles: bb = tau>>5, w0 = (tau&31)*256
#define NCTA     152

__global__ void __launch_bounds__(512, 1) h_mma_kernel(
    const float* __restrict__ ctx_b,
    const float* __restrict__ seW_b)
{
    extern __shared__ char smc[];
    uint32_t sbase = smem_u32(smc);
    const int t   = threadIdx.x;
    const int wid = t >> 5;
    const int l   = t & 31;

    const uint32_t Bo[2] = {HP_B0, HP_B1};

    const int per = H_NT / NCTA;           // 10
    const int rem = H_NT % NCTA;           // 16
    const int cta = blockIdx.x;
    int start = cta * per + (cta < rem ? cta : rem);
    int cnt = per + (cta < rem ? 1 : 0);

    // ---- stage BC once + tile `start` into buf 0 (one group) ----
    for (int i = t; i < 64 * 24; i += 512) {
        int f = i / 24, c = i - f * 24;
        cp_async16(sbase + HP_BC + f * 400 + c * 16, g_cwBh + f * 192 + c * 8);
    }
    {
        int tau = start;
        int bb = tau >> 5, w0 = (tau & 31) * 256;
        const __half* xhb = g_xh + (size_t)bb * Wn * Fc;
        for (int i = t; i < 258 * 8; i += 512) {
            int j = i >> 3, c = i & 7;
            int gr = w0 - 1 + j;
            if (gr >= 0 && gr < Wn)
                cp_async16(sbase + HP_B0 + j * 144 + c * 16, xhb + (size_t)gr * Fc + c * 8);
            else
                *(uint4*)(smc + HP_B0 + j * 144 + c * 16) = make_uint4(0, 0, 0, 0);
        }
        for (int i = t; i < 256 * 8; i += 512) {
            int r = i >> 3, c = i & 7;
            cp_async16(sbase + HP_B0 + HP_AS_O + r * 144 + c * 16,
                       g_sewh + (size_t)(w0 + r) * Fc + c * 8);
        }
        for (int i = t; i < 64 * 8; i += 512) {
            int f = i >> 3, c = i & 7;
            cp_async16(sbase + HP_B0 + HP_BG_O + f * 144 + c * 16,
                       g_gramh + bb * 4096 + f * 64 + c * 8);
        }
    }
    cp_commit();

    const int fg = wid & 1;                // f0 = fg*32
    const int wg = wid >> 1;               // R = wg*32
    const int R  = wg * 32;
    const int f0 = fg * 32;
    const int rl = l & 15;
    const uint32_t ch = (uint32_t)(l >> 4) * 16;
    const uint32_t aBC = sbase + HP_BC + (uint32_t)(f0 + rl) * 400 + ch;
    const int gr  = l >> 2;
    const int gc2 = (l & 3) * 2;

    for (int it = 0; it < cnt; it++) {
        int buf = it & 1;
        // ---- prefetch next tile into other buffer ----
        if (it + 1 < cnt) {
            int tau2 = start + it + 1;
            int bb2 = tau2 >> 5, w02 = (tau2 & 31) * 256;
            uint32_t nb = Bo[buf ^ 1];
            const __half* xhb2 = g_xh + (size_t)bb2 * Wn * Fc;
            for (int i = t; i < 258 * 8; i += 512) {
                int j = i >> 3, c = i & 7;
                int grr = w02 - 1 + j;
                if (grr >= 0 && grr < Wn)
                    cp_async16(sbase + nb + j * 144 + c * 16,
                               xhb2 + (size_t)grr * Fc + c * 8);
                else
                    *(uint4*)(smc + nb + j * 144 + c * 16) = make_uint4(0, 0, 0, 0);
            }
            for (int i = t; i < 256 * 8; i += 512) {
                int r = i >> 3, c = i & 7;
                cp_async16(sbase + nb + HP_AS_O + r * 144 + c * 16,
                           g_sewh + (size_t)(w02 + r) * Fc + c * 8);
            }
            for (int i = t; i < 64 * 8; i += 512) {
                int f = i >> 3, c = i & 7;
                cp_async16(sbase + nb + HP_BG_O + f * 144 + c * 16,
                           g_gramh + bb2 * 4096 + f * 64 + c * 8);
            }
            cp_commit();
            cp_wait1();
        } else {
            cp_wait0();
        }
        __syncthreads();

        // ---- compute tile it from buf ----
        int tau = start + it;
        int bb = tau >> 5, w0 = (tau & 31) * 256;
        uint32_t bbase_off = Bo[buf];
        uint32_t aAX = sbase + bbase_off + (uint32_t)(R + rl) * 144 + ch;
        uint32_t aAS = sbase + bbase_off + HP_AS_O + (uint32_t)(R + rl) * 144 + ch;
        uint32_t aBG = sbase + bbase_off + HP_BG_O + (uint32_t)(f0 + rl) * 144 + ch;

        float acc[2][4][4];
        #pragma unroll
        for (int i = 0; i < 2; i++)
            #pragma unroll
            for (int j = 0; j < 4; j++)
                #pragma unroll
                for (int q = 0; q < 4; q++) acc[i][j][q] = 0.f;

        // SE GEMM: K=64 -> 4 k16-steps
        #pragma unroll
        for (int s = 0; s < 4; s++) {
            uint32_t fa0[4], fa1[4], fb0[4], fb1[4];
            ldsm_x4(aAS + 32u * s, fa0);
            ldsm_x4(aAS + 16u * 144 + 32u * s, fa1);
            ldsm_x4(aBG + 32u * s, fb0);
            ldsm_x4(aBG + 16u * 144 + 32u * s, fb1);
            mma_f16(acc[0][0], fa0, fb0[0], fb0[2]);
            mma_f16(acc[0][1], fa0, fb0[1], fb0[3]);
            mma_f16(acc[0][2], fa0, fb1[0], fb1[2]);
            mma_f16(acc[0][3], fa0, fb1[1], fb1[3]);
            mma_f16(acc[1][0], fa1, fb0[0], fb0[2]);
            mma_f16(acc[1][1], fa1, fb0[1], fb0[3]);
            mma_f16(acc[1][2], fa1, fb1[0], fb1[2]);
            mma_f16(acc[1][3], fa1, fb1[1], fb1[3]);
        }

        // transform in place: acc = relu(acc + seb) + ctx_b
        {
            int row0 = w0 + R + gr;
            float seb[4];
            seb[0] = __ldg(seW_b + row0);
            seb[1] = __ldg(seW_b + row0 + 8);
            seb[2] = __ldg(seW_b + row0 + 16);
            seb[3] = __ldg(seW_b + row0 + 24);
            #pragma unroll
            for (int mt = 0; mt < 2; mt++) {
                float s0 = seb[mt * 2], s1 = seb[mt * 2 + 1];
                #pragma unroll
                for (int ntile = 0; ntile < 4; ntile++) {
                    int col = f0 + ntile * 8 + gc2;
                    float c0 = __ldg(ctx_b + col), c1 = __ldg(ctx_b + col + 1);
                    float* a = acc[mt][ntile];
                    a[0] = fmaxf(a[0] + s0, 0.f) + c0;
                    a[1] = fmaxf(a[1] + s0, 0.f) + c1;
                    a[2] = fmaxf(a[2] + s1, 0.f) + c0;
                    a[3] = fmaxf(a[3] + s1, 0.f) + c1;
                }
            }
        }

        // conv GEMM: 3 passes (A row shift) x 4 k16-steps
        #pragma unroll
        for (int pass = 0; pass < 3; pass++) {
            uint32_t abase = aAX + (uint32_t)pass * 144;
            uint32_t bcb   = aBC + (uint32_t)pass * 128;
            #pragma unroll
            for (int s = 0; s < 4; s++) {
                uint32_t fa0[4], fa1[4], fb0[4], fb1[4];
                ldsm_x4(abase + 32u * s, fa0);
                ldsm_x4(abase + 16u * 144 + 32u * s, fa1);
                ldsm_x4(bcb + 32u * s, fb0);
                ldsm_x4(bcb + 16u * 400 + 32u * s, fb1);
                mma_f16(acc[0][0], fa0, fb0[0], fb0[2]);
                mma_f16(acc[0][1], fa0, fb0[1], fb0[3]);
                mma_f16(acc[0][2], fa0, fb1[0], fb1[2]);
                mma_f16(acc[0][3], fa0, fb1[1], fb1[3]);
                mma_f16(acc[1][0], fa1, fb0[0], fb0[2]);
                mma_f16(acc[1][1], fa1, fb0[1], fb0[3]);
                mma_f16(acc[1][2], fa1, fb1[0], fb1[2]);
                mma_f16(acc[1][3], fa1, fb1[1], fb1[3]);
            }
        }

        // store h (fp16)
        #pragma unroll
        for (int mt = 0; mt < 2; mt++) {
            int row0 = w0 + R + mt * 16 + gr;
            #pragma unroll
            for (int ntile = 0; ntile < 4; ntile++) {
                const float* a = acc[mt][ntile];
                __half* h0 = g_hh + ((size_t)bb * Wn + row0) * Fc + f0 + ntile * 8 + gc2;
                __half2 p0 = __floats2half2_rn(a[0], a[1]);
                __half2 p1 = __floats2half2_rn(a[2], a[3]);
                *(__half2*)(h0) = p0;
                *(__half2*)(h0 + 8 * Fc) = p1;
            }
        }
        __syncthreads();
    }
}

// ---------------------------------------------------------------------------
// Kernel O (persistent, mma.sync fp16, d-split, 2 CTAs/SM, double-buffered A):
// R15/R16 winner, unchanged.
// ---------------------------------------------------------------------------
#define OMS_B    0                        // 64*400 = 25600
#define OMS_A0   25600                    // 130*144 = 18720
#define OMS_A1   44320
#define OMS_SMEM 63040
#define O_NT     3072

__global__ void __launch_bounds__(256, 2) out_mma_kernel(float* __restrict__ out)
{
    extern __shared__ char smc[];
    uint32_t sbase = smem_u32(smc);
    const int t   = threadIdx.x;
    const int wid = t >> 5;
    const int l   = t & 31;

    const uint32_t Ao[2] = {OMS_A0, OMS_A1};

    const int half = blockIdx.x >= 152;
    const int cta  = blockIdx.x - half * 152;
    const int d_base = half * 64;

    const int per = O_NT / 152;
    const int rem = O_NT % 152;
    int start = cta * per + (cta < rem ? cta : rem);
    int cnt = per + (cta < rem ? 1 : 0);

    for (int i = t; i < 64 * 24; i += 256) {
        int d = i / 24, c = i - d * 24;
        cp_async16(sbase + OMS_B + d * 400 + c * 16,
                   g_twBh + (d_base + d) * 192 + c * 8);
    }
    {
        int tau = start;
        int bb = tau >> 6, w0 = (tau & 63) * 128;
        const __half* hb = g_hh + (size_t)bb * Wn * Fc;
        for (int i = t; i < 130 * 8; i += 256) {
            int j = i >> 3, c = i & 7;
            int gw = (w0 - 1 + j + Wn) & (Wn - 1);
            cp_async16(sbase + OMS_A0 + j * 144 + c * 16, hb + (size_t)gw * Fc + c * 8);
        }
    }
    cp_commit();

    const int wg = wid & 3;
    const int dg = wid >> 2;
    const int R  = wg * 32;
    const int D  = dg * 32;
    const int rl = l & 15;
    const uint32_t ch = (uint32_t)(l >> 4) * 16;
    const uint32_t aB = sbase + OMS_B + (uint32_t)(D + rl) * 400 + ch;
    const int gr  = l >> 2;
    const int gc2 = (l & 3) * 2;

    for (int it = 0; it < cnt; it++) {
        int buf = it & 1;
        if (it + 1 < cnt) {
            int tau2 = start + it + 1;
            int bb2 = tau2 >> 6, w02 = (tau2 & 63) * 128;
            const __half* hb2 = g_hh + (size_t)bb2 * Wn * Fc;
            int nb = buf ^ 1;
            for (int i = t; i < 130 * 8; i += 256) {
                int j = i >> 3, c = i & 7;
                int gw = (w02 - 1 + j + Wn) & (Wn - 1);
                cp_async16(sbase + Ao[nb] + j * 144 + c * 16,
                           hb2 + (size_t)gw * Fc + c * 8);
            }
            cp_commit();
            cp_wait1();
        } else {
            cp_wait0();
        }
        __syncthreads();

        int tau = start + it;
        int bb = tau >> 6, w0 = (tau & 63) * 128;
        uint32_t aA = sbase + Ao[buf] + (uint32_t)(R + rl) * 144 + ch;

        float acc[2][4][4];
        #pragma unroll
        for (int i = 0; i < 2; i++)
            #pragma unroll
            for (int j = 0; j < 4; j++)
                #pragma unroll
                for (int q = 0; q < 4; q++) acc[i][j][q] = 0.f;

        #pragma unroll
        for (int pass = 0; pass < 3; pass++) {
            uint32_t abase = aA + (uint32_t)pass * 144;
            uint32_t bbase = aB + (uint32_t)pass * 128;
            #pragma unroll
            for (int s = 0; s < 4; s++) {
                uint32_t fa0[4], fa1[4], fb0[4], fb1[4];
                ldsm_x4(abase + 32u * s, fa0);
                ldsm_x4(abase + 16u * 144 + 32u * s, fa1);
                ldsm_x4(bbase + 32u * s, fb0);
                ldsm_x4(bbase + 16u * 400 + 32u * s, fb1);
                mma_f16(acc[0][0], fa0, fb0[0], fb0[2]);
                mma_f16(acc[0][1], fa0, fb0[1], fb0[3]);
                mma_f16(acc[0][2], fa0, fb1[0], fb1[2]);
                mma_f16(acc[0][3], fa0, fb1[1], fb1[3]);
                mma_f16(acc[1][0], fa1, fb0[0], fb0[2]);
                mma_f16(acc[1][1], fa1, fb0[1], fb0[3]);
                mma_f16(acc[1][2], fa1, fb1[0], fb1[2]);
                mma_f16(acc[1][3], fa1, fb1[1], fb1[3]);
            }
        }

        #pragma unroll
        for (int mt = 0; mt < 2; mt++) {
            #pragma unroll
            for (int ntile = 0; ntile < 4; ntile++) {
                const float* c = acc[mt][ntile];
                int w_row = w0 + R + mt * 16 + gr;
                int d_col = d_base + D + ntile * 8 + gc2;
                float* ob = out + ((size_t)bb * Wn + w_row) * Dc + d_col;
                *(float2*)(ob)          = make_float2(c[0], c[1]);
                *(float2*)(ob + 8 * Dc) = make_float2(c[2], c[3]);
            }
        }
        __syncthreads();
    }
}

// ---------------------------------------------------------------------------
extern "C" void kernel_launch(void* const* d_in, const int* in_sizes, int n_in,
                              void* d_out, int out_size) {
    const float* x       = (const float*)d_in[0];
    const float* ctx_w   = (const float*)d_in[1];
    const float* ctx_b   = (const float*)d_in[2];
    const float* token_w = (const float*)d_in[3];
    const float* seW_w   = (const float*)d_in[4];
    const float* seW_b   = (const float*)d_in[5];
    float* out = (float*)d_out;

    cudaFuncSetAttribute(h_mma_kernel,
                         cudaFuncAttributeMaxDynamicSharedMemorySize, HP_SMEM);
    cudaFuncSetAttribute(out_mma_kernel,
                         cudaFuncAttributeMaxDynamicSharedMemorySize, OMS_SMEM);

    gram_mma<<<dim3(GRAM_CHUNKS, Bc), 128>>>(x);
    prep_kernel<<<96, 256>>>(ctx_w, token_w, seW_w);
    gram_reduce<<<Bc, 256>>>();
    h_mma_kernel<<<NCTA, 512, HP_SMEM>>>(ctx_b, seW_b);
    out_mma_kernel<<<304, 256, OMS_SMEM>>>(out);
}